// round 1
// baseline (speedup 1.0000x reference)
#include <cuda_runtime.h>
#include <math.h>

// Problem constants (fixed by the reference)
#define BB     4
#define LL     8192
#define DD     1024
#define HH     16
#define DH     64
#define MLROWS (BB * LL)          // 32768
#define EPSV   1e-6f
#define SPLITS 16
#define LCHUNK (LL / SPLITS)      // 512

// ---------------- scratch (static device globals; no allocation) ----------
__device__ float g_Qf[MLROWS * DD];               // phi(x @ Wq)
__device__ float g_Kf[MLROWS * DD];               // phi(x @ Wk)
__device__ float g_V [MLROWS * DD];               // x @ Wv
__device__ float g_att[MLROWS * DD];              // attention output pre-Wo
__device__ float g_KvPart[BB * HH * SPLITS * DH * DH];
__device__ float g_K1Part[BB * HH * SPLITS * DH];
__device__ float g_Kv[BB * HH * DH * DH];
__device__ float g_K1[BB * HH * DH];

// ---------------- 128x128x8 SGEMM, 256 threads, 8x8 per-thread tile -------
// C[M,N] = A[M,K] * W[K,N], row-major. PHI=1 applies phi(v)=elu(v)+1.
template <int PHI>
__global__ __launch_bounds__(256, 2)
void sgemm_k(const float* __restrict__ A, const float* __restrict__ W,
             float* __restrict__ C) {
    const int N = DD, K = DD;
    __shared__ float As[8][128];   // transposed A tile
    __shared__ float Bs[8][128];

    const int tid = threadIdx.x;
    const int bm  = blockIdx.y * 128;
    const int bn  = blockIdx.x * 128;
    const int tx  = tid & 15;      // n-dir (16)
    const int ty  = tid >> 4;      // m-dir (16)

    float acc[8][8];
#pragma unroll
    for (int i = 0; i < 8; ++i)
#pragma unroll
        for (int j = 0; j < 8; ++j) acc[i][j] = 0.f;

    const int arow = tid >> 1;           // 0..127
    const int acol = (tid & 1) * 4;      // 0 or 4
    const int brow = tid >> 5;           // 0..7
    const int bcol = (tid & 31) * 4;     // 0..124

    const float* Ap = A + (size_t)(bm + arow) * K + acol;
    const float* Wp = W + (size_t)brow * N + bn + bcol;

    for (int k0 = 0; k0 < K; k0 += 8) {
        float4 av = *(const float4*)(Ap + k0);
        As[acol + 0][arow] = av.x;
        As[acol + 1][arow] = av.y;
        As[acol + 2][arow] = av.z;
        As[acol + 3][arow] = av.w;
        *(float4*)&Bs[brow][bcol] = *(const float4*)(Wp + (size_t)k0 * N);
        __syncthreads();

#pragma unroll
        for (int kk = 0; kk < 8; ++kk) {
            float ar[8], br[8];
            *(float4*)(ar)     = *(float4*)&As[kk][ty * 8];
            *(float4*)(ar + 4) = *(float4*)&As[kk][ty * 8 + 4];
            *(float4*)(br)     = *(float4*)&Bs[kk][tx * 8];
            *(float4*)(br + 4) = *(float4*)&Bs[kk][tx * 8 + 4];
#pragma unroll
            for (int i = 0; i < 8; ++i)
#pragma unroll
                for (int j = 0; j < 8; ++j)
                    acc[i][j] = fmaf(ar[i], br[j], acc[i][j]);
        }
        __syncthreads();
    }

#pragma unroll
    for (int i = 0; i < 8; ++i) {
        float* Crow = C + (size_t)(bm + ty * 8 + i) * N + bn + tx * 8;
#pragma unroll
        for (int j = 0; j < 8; ++j) {
            float v = acc[i][j];
            if (PHI) v = (v > 0.f) ? (v + 1.f) : expf(v);   // elu(v)+1
            acc[i][j] = v;
        }
        *(float4*)(Crow)     = *(float4*)&acc[i][0];
        *(float4*)(Crow + 4) = *(float4*)&acc[i][4];
    }
}

// ---------- Kv = sum_l Kf[l,:]^T V[l,:]  and K1 = sum_l Kf[l,:] -----------
// grid: (B*H, SPLITS). Each block reduces 512 L-rows into a 64x64 partial.
__global__ __launch_bounds__(256)
void kv_part_k() {
    const int bh    = blockIdx.x;        // 0..63
    const int split = blockIdx.y;        // 0..15
    const int b = bh >> 4, h = bh & 15;

    __shared__ float Ks[32][64];
    __shared__ float Vs[32][64];

    const int tid = threadIdx.x;
    const int tx  = tid & 15;            // n (4 cols)
    const int ty  = tid >> 4;            // m (4 rows)

    float acc[4][4];
#pragma unroll
    for (int i = 0; i < 4; ++i)
#pragma unroll
        for (int j = 0; j < 4; ++j) acc[i][j] = 0.f;
    float k1a[4] = {0.f, 0.f, 0.f, 0.f};

    const size_t base = ((size_t)b * LL) * DD + (size_t)h * DH;
    const int l0 = split * LCHUNK;

    for (int lt = 0; lt < LCHUNK; lt += 32) {
#pragma unroll
        for (int t = 0; t < 2; ++t) {
            int v = tid + t * 256;               // 0..511 (float4 index)
            int r = v >> 4;                      // 0..31
            int c = (v & 15) << 2;               // 0..60
            size_t g = base + (size_t)(l0 + lt + r) * DD + c;
            *(float4*)&Ks[r][c] = *(const float4*)(g_Kf + g);
            *(float4*)&Vs[r][c] = *(const float4*)(g_V  + g);
        }
        __syncthreads();
#pragma unroll 8
        for (int r = 0; r < 32; ++r) {
            float a0 = Ks[r][ty * 4 + 0], a1 = Ks[r][ty * 4 + 1];
            float a2 = Ks[r][ty * 4 + 2], a3 = Ks[r][ty * 4 + 3];
            float b0 = Vs[r][tx * 4 + 0], b1 = Vs[r][tx * 4 + 1];
            float b2 = Vs[r][tx * 4 + 2], b3 = Vs[r][tx * 4 + 3];
            acc[0][0] = fmaf(a0, b0, acc[0][0]); acc[0][1] = fmaf(a0, b1, acc[0][1]);
            acc[0][2] = fmaf(a0, b2, acc[0][2]); acc[0][3] = fmaf(a0, b3, acc[0][3]);
            acc[1][0] = fmaf(a1, b0, acc[1][0]); acc[1][1] = fmaf(a1, b1, acc[1][1]);
            acc[1][2] = fmaf(a1, b2, acc[1][2]); acc[1][3] = fmaf(a1, b3, acc[1][3]);
            acc[2][0] = fmaf(a2, b0, acc[2][0]); acc[2][1] = fmaf(a2, b1, acc[2][1]);
            acc[2][2] = fmaf(a2, b2, acc[2][2]); acc[2][3] = fmaf(a2, b3, acc[2][3]);
            acc[3][0] = fmaf(a3, b0, acc[3][0]); acc[3][1] = fmaf(a3, b1, acc[3][1]);
            acc[3][2] = fmaf(a3, b2, acc[3][2]); acc[3][3] = fmaf(a3, b3, acc[3][3]);
            k1a[0] += a0; k1a[1] += a1; k1a[2] += a2; k1a[3] += a3;
        }
        __syncthreads();
    }

    float* kp = g_KvPart + ((size_t)bh * SPLITS + split) * (DH * DH);
#pragma unroll
    for (int i = 0; i < 4; ++i)
#pragma unroll
        for (int j = 0; j < 4; ++j)
            kp[(ty * 4 + i) * DH + tx * 4 + j] = acc[i][j];
    if (tx == 0) {
        float* k1p = g_K1Part + ((size_t)bh * SPLITS + split) * DH;
#pragma unroll
        for (int i = 0; i < 4; ++i) k1p[ty * 4 + i] = k1a[i];
    }
}

// ---------------- reduce split partials --------------------------------
__global__ __launch_bounds__(256)
void kv_reduce_k() {
    const int bh  = blockIdx.x;
    const int tid = threadIdx.x;
    for (int idx = tid; idx < DH * DH; idx += 256) {
        float s = 0.f;
#pragma unroll
        for (int sp = 0; sp < SPLITS; ++sp)
            s += g_KvPart[((size_t)bh * SPLITS + sp) * (DH * DH) + idx];
        g_Kv[(size_t)bh * (DH * DH) + idx] = s;
    }
    if (tid < DH) {
        float s = 0.f;
#pragma unroll
        for (int sp = 0; sp < SPLITS; ++sp)
            s += g_K1Part[((size_t)bh * SPLITS + sp) * DH + tid];
        g_K1[bh * DH + tid] = s;
    }
}

// -------- att[l,n] = (Qf[l,:] @ Kv[:,n]) / (Qf[l,:] @ K1 + eps) ---------
// grid: (B*H, L/64). Each block: 64 L-rows x 64 cols for one (b,h).
__global__ __launch_bounds__(256)
void numden_k() {
    const int bh = blockIdx.x;           // 0..63
    const int lt = blockIdx.y;           // 0..127
    const int b = bh >> 4, h = bh & 15;

    __shared__ float Kvs[64][64];
    __shared__ float Qs[64][64];
    __shared__ float K1s[64];

    const int tid = threadIdx.x;
    const int tx  = tid & 15;
    const int ty  = tid >> 4;

    const size_t base = ((size_t)b * LL + (size_t)lt * 64) * DD + (size_t)h * DH;

    {   // Kv is contiguous -> straight float4 copy
        const float4* src = (const float4*)(g_Kv + (size_t)bh * DH * DH);
        float4* dst = (float4*)&Kvs[0][0];
#pragma unroll
        for (int t = 0; t < 4; ++t) dst[tid + t * 256] = src[tid + t * 256];
    }
#pragma unroll
    for (int t = 0; t < 4; ++t) {        // Qf tile 64x64
        int v = tid + t * 256;
        int r = v >> 4, c = (v & 15) << 2;
        *(float4*)&Qs[r][c] = *(const float4*)(g_Qf + base + (size_t)r * DD + c);
    }
    if (tid < DH) K1s[tid] = g_K1[bh * DH + tid];
    __syncthreads();

    float acc[4][4];
#pragma unroll
    for (int i = 0; i < 4; ++i)
#pragma unroll
        for (int j = 0; j < 4; ++j) acc[i][j] = 0.f;
    float den[4] = {0.f, 0.f, 0.f, 0.f};   // redundant across tx; avoids a
                                           // conflicted reduction phase
#pragma unroll 8
    for (int m = 0; m < 64; ++m) {
        float k1m = K1s[m];
        float a0 = Qs[ty * 4 + 0][m], a1 = Qs[ty * 4 + 1][m];
        float a2 = Qs[ty * 4 + 2][m], a3 = Qs[ty * 4 + 3][m];
        float b0 = Kvs[m][tx * 4 + 0], b1 = Kvs[m][tx * 4 + 1];
        float b2 = Kvs[m][tx * 4 + 2], b3 = Kvs[m][tx * 4 + 3];
        acc[0][0] = fmaf(a0, b0, acc[0][0]); acc[0][1] = fmaf(a0, b1, acc[0][1]);
        acc[0][2] = fmaf(a0, b2, acc[0][2]); acc[0][3] = fmaf(a0, b3, acc[0][3]);
        acc[1][0] = fmaf(a1, b0, acc[1][0]); acc[1][1] = fmaf(a1, b1, acc[1][1]);
        acc[1][2] = fmaf(a1, b2, acc[1][2]); acc[1][3] = fmaf(a1, b3, acc[1][3]);
        acc[2][0] = fmaf(a2, b0, acc[2][0]); acc[2][1] = fmaf(a2, b1, acc[2][1]);
        acc[2][2] = fmaf(a2, b2, acc[2][2]); acc[2][3] = fmaf(a2, b3, acc[2][3]);
        acc[3][0] = fmaf(a3, b0, acc[3][0]); acc[3][1] = fmaf(a3, b1, acc[3][1]);
        acc[3][2] = fmaf(a3, b2, acc[3][2]); acc[3][3] = fmaf(a3, b3, acc[3][3]);
        den[0] = fmaf(a0, k1m, den[0]); den[1] = fmaf(a1, k1m, den[1]);
        den[2] = fmaf(a2, k1m, den[2]); den[3] = fmaf(a3, k1m, den[3]);
    }

#pragma unroll
    for (int i = 0; i < 4; ++i) {
        int r = ty * 4 + i;
        float inv = 1.f / (den[i] + EPSV);
        float4 o;
        o.x = acc[i][0] * inv; o.y = acc[i][1] * inv;
        o.z = acc[i][2] * inv; o.w = acc[i][3] * inv;
        *(float4*)(g_att + base + (size_t)r * DD + tx * 4) = o;
    }
}

// --------------------------- host launch --------------------------------
extern "C" void kernel_launch(void* const* d_in, const int* in_sizes, int n_in,
                              void* d_out, int out_size) {
    const float* x  = (const float*)d_in[0];
    const float* Wq = (const float*)d_in[1];
    const float* Wk = (const float*)d_in[2];
    const float* Wv = (const float*)d_in[3];
    const float* Wo = (const float*)d_in[4];
    float* out = (float*)d_out;

    float *qf, *kf, *v, *att;
    cudaGetSymbolAddress((void**)&qf,  g_Qf);
    cudaGetSymbolAddress((void**)&kf,  g_Kf);
    cudaGetSymbolAddress((void**)&v,   g_V);
    cudaGetSymbolAddress((void**)&att, g_att);

    dim3 gg(DD / 128, MLROWS / 128);          // (8, 256)
    sgemm_k<1><<<gg, 256>>>(x, Wq, qf);       // Qf = phi(x @ Wq)
    sgemm_k<1><<<gg, 256>>>(x, Wk, kf);       // Kf = phi(x @ Wk)
    sgemm_k<0><<<gg, 256>>>(x, Wv, v);        // V  = x @ Wv

    kv_part_k<<<dim3(BB * HH, SPLITS), 256>>>();
    kv_reduce_k<<<BB * HH, 256>>>();
    numden_k<<<dim3(BB * HH, LL / 64), 256>>>();

    sgemm_k<0><<<gg, 256>>>(att, Wo, out);    // out = att @ Wo
}

// round 5
// speedup vs baseline: 2.2925x; 2.2925x over previous
#include <cuda_runtime.h>
#include <cuda_bf16.h>
#include <stdint.h>
#include <math.h>

// Problem constants (fixed by the reference)
#define BB     4
#define LL     8192
#define DD     1024
#define HH     16
#define DH     64
#define MLROWS (BB * LL)          // 32768
#define EPSV   1e-6f
#define SPLITS 16
#define LCHUNK (LL / SPLITS)      // 512

// GEMM tiling: CTA 128x128, 8 warps (4x2), warp tile 32x64, K-chunk 64
#define KC 64
#define GEMM_SMEM (64 * 1024)

// ---------------- scratch (static device globals; no allocation) ----------
__device__ float g_Qf[MLROWS * DD];
__device__ float g_Kf[MLROWS * DD];
__device__ float g_V [MLROWS * DD];
__device__ float g_att[MLROWS * DD];
__device__ float g_KvPart[BB * HH * SPLITS * DH * DH];
__device__ float g_K1Part[BB * HH * SPLITS * DH];
__device__ float g_Kv[BB * HH * DH * DH];
__device__ float g_K1[BB * HH * DH];
// transposed + hi/lo split weights: [4][N=1024][K=1024] bf16
__device__ __nv_bfloat16 g_Wth[4][DD * DD];
__device__ __nv_bfloat16 g_Wtl[4][DD * DD];

// =========================== helpers ==================================
__device__ __forceinline__ uint32_t smem_u32(const void* p) {
    return (uint32_t)__cvta_generic_to_shared(p);
}

__device__ __forceinline__ void split2(float a, float b, uint32_t& hw, uint32_t& lw) {
    __nv_bfloat16 ha = __float2bfloat16(a);
    __nv_bfloat16 hb = __float2bfloat16(b);
    __nv_bfloat16 la = __float2bfloat16(a - __bfloat162float(ha));
    __nv_bfloat16 lb = __float2bfloat16(b - __bfloat162float(hb));
    hw = (uint32_t)__bfloat16_as_ushort(ha) | ((uint32_t)__bfloat16_as_ushort(hb) << 16);
    lw = (uint32_t)__bfloat16_as_ushort(la) | ((uint32_t)__bfloat16_as_ushort(lb) << 16);
}

#define LDSM_X4(r0, r1, r2, r3, addr) \
    asm volatile("ldmatrix.sync.aligned.m8n8.x4.shared.b16 {%0,%1,%2,%3}, [%4];" \
                 : "=r"(r0), "=r"(r1), "=r"(r2), "=r"(r3) : "r"(addr))

#define MMA16816(d, a, b0, b1) \
    asm volatile("mma.sync.aligned.m16n8k16.row.col.f32.bf16.bf16.f32 " \
                 "{%0,%1,%2,%3}, {%4,%5,%6,%7}, {%8,%9}, {%0,%1,%2,%3};" \
                 : "+f"((d)[0]), "+f"((d)[1]), "+f"((d)[2]), "+f"((d)[3]) \
                 : "r"((a)[0]), "r"((a)[1]), "r"((a)[2]), "r"((a)[3]), \
                   "r"(b0), "r"(b1))

// ================= weight pre-pass: W[K,N] -> Wt_hi/lo[N,K] bf16 ==========
__global__ __launch_bounds__(256)
void wsplit_k(const float* __restrict__ W,
              __nv_bfloat16* __restrict__ Th,
              __nv_bfloat16* __restrict__ Tl) {
    __shared__ float t[32][33];
    const int nb = blockIdx.x * 32;
    const int kb = blockIdx.y * 32;
    const int tx = threadIdx.x & 31;
    const int ty = threadIdx.x >> 5;     // 0..7
    for (int i = ty; i < 32; i += 8)
        t[i][tx] = W[(size_t)(kb + i) * DD + nb + tx];   // t[k_local][n_local]
    __syncthreads();
    for (int i = ty; i < 32; i += 8) {
        float v = t[tx][i];              // k_local = tx, n_local = i
        __nv_bfloat16 h = __float2bfloat16(v);
        __nv_bfloat16 l = __float2bfloat16(v - __bfloat162float(h));
        size_t o = (size_t)(nb + i) * DD + kb + tx;
        Th[o] = h; Tl[o] = l;
    }
}

// ================= mma.sync bf16 GEMM =====================================
// C[M,N] = A[M,K] * W[K,N], W given transposed [N,K] as hi/lo bf16.
// 3-term split: Ah*Wh + Al*Wh + Ah*Wl, fp32 accumulate.

__device__ __forceinline__ void ldg_chunk(
    const float* __restrict__ A, const __nv_bfloat16* __restrict__ Bh,
    const __nv_bfloat16* __restrict__ Bl, int bm, int bn, int k0, int tid,
    float4 ra[8], uint4 rbh[4], uint4 rbl[4]) {
#pragma unroll
    for (int t = 0; t < 8; ++t) {
        int idx = tid + t * 256;
        int row = idx >> 4;              // 0..127
        int c4  = (idx & 15) << 2;       // 0..60
        ra[t] = *(const float4*)(A + (size_t)(bm + row) * DD + k0 + c4);
    }
#pragma unroll
    for (int t = 0; t < 4; ++t) {
        int idx = tid + t * 256;         // 0..1023
        int row = idx >> 3;              // 0..127
        int kk  = (idx & 7) << 3;        // 0..56 (bf16 elems, x8 per uint4)
        rbh[t] = *(const uint4*)(Bh + (size_t)(bn + row) * DD + k0 + kk);
        rbl[t] = *(const uint4*)(Bl + (size_t)(bn + row) * DD + k0 + kk);
    }
}

__device__ __forceinline__ void sts_chunk(
    char* pAh, char* pAl, char* pBh, char* pBl, int tid,
    const float4 ra[8], const uint4 rbh[4], const uint4 rbl[4]) {
#pragma unroll
    for (int t = 0; t < 8; ++t) {
        int idx = tid + t * 256;
        int row = idx >> 4;
        int c4  = (idx & 15) << 2;
        uint32_t h0, l0, h1, l1;
        split2(ra[t].x, ra[t].y, h0, l0);
        split2(ra[t].z, ra[t].w, h1, l1);
        uint32_t off = (uint32_t)(row * 128 + c4 * 2);
        uint32_t sw  = off ^ ((off >> 3) & 0x70);
        *(uint2*)(pAh + sw) = make_uint2(h0, h1);
        *(uint2*)(pAl + sw) = make_uint2(l0, l1);
    }
#pragma unroll
    for (int t = 0; t < 4; ++t) {
        int idx = tid + t * 256;         // 0..1023
        int row = idx >> 3;              // 0..127
        int kb  = (idx & 7) << 4;        // 0..112 bytes
        uint32_t off = (uint32_t)(row * 128 + kb);
        uint32_t sw  = off ^ ((off >> 3) & 0x70);
        *(uint4*)(pBh + sw) = rbh[t];
        *(uint4*)(pBl + sw) = rbl[t];
    }
}

__device__ __forceinline__ void compute_chunk(
    uint32_t sAh, uint32_t sAl, uint32_t sBh, uint32_t sBl,
    int wm, int wn, int lane, float acc[2][8][4]) {
    const int i   = lane & 7;
    const int sub = lane >> 3;
#pragma unroll
    for (int ks = 0; ks < 4; ++ks) {
        uint32_t ah[2][4], al[2][4], bh[8][2], bl[8][2];
#pragma unroll
        for (int mt = 0; mt < 2; ++mt) {
            int row = wm * 32 + mt * 16 + i + ((sub & 1) << 3);
            int kk  = ks * 16 + ((sub & 2) << 2);
            uint32_t off = (uint32_t)(row * 128 + kk * 2);
            uint32_t sw  = off ^ ((off >> 3) & 0x70);
            LDSM_X4(ah[mt][0], ah[mt][1], ah[mt][2], ah[mt][3], sAh + sw);
            LDSM_X4(al[mt][0], al[mt][1], al[mt][2], al[mt][3], sAl + sw);
        }
#pragma unroll
        for (int np = 0; np < 4; ++np) {
            int row = wn * 64 + np * 16 + i + ((sub & 2) << 2);
            int kk  = ks * 16 + ((sub & 1) << 3);
            uint32_t off = (uint32_t)(row * 128 + kk * 2);
            uint32_t sw  = off ^ ((off >> 3) & 0x70);
            uint32_t r0, r1, r2, r3;
            LDSM_X4(r0, r1, r2, r3, sBh + sw);
            bh[2 * np][0] = r0; bh[2 * np][1] = r1;
            bh[2 * np + 1][0] = r2; bh[2 * np + 1][1] = r3;
            LDSM_X4(r0, r1, r2, r3, sBl + sw);
            bl[2 * np][0] = r0; bl[2 * np][1] = r1;
            bl[2 * np + 1][0] = r2; bl[2 * np + 1][1] = r3;
        }
#pragma unroll
        for (int mt = 0; mt < 2; ++mt)
#pragma unroll
            for (int nt = 0; nt < 8; ++nt) {
                MMA16816(acc[mt][nt], ah[mt], bh[nt][0], bh[nt][1]);
                MMA16816(acc[mt][nt], al[mt], bh[nt][0], bh[nt][1]);
                MMA16816(acc[mt][nt], ah[mt], bl[nt][0], bl[nt][1]);
            }
    }
}

template <int PHI>
__global__ __launch_bounds__(256)
void mma_gemm_k(const float* __restrict__ A,
                const __nv_bfloat16* __restrict__ Bh,
                const __nv_bfloat16* __restrict__ Bl,
                float* __restrict__ C) {
    extern __shared__ char sm[];
    char* pAh = sm;
    char* pAl = sm + 16 * 1024;
    char* pBh = sm + 32 * 1024;
    char* pBl = sm + 48 * 1024;
    const uint32_t sAh = smem_u32(pAh);
    const uint32_t sAl = smem_u32(pAl);
    const uint32_t sBh = smem_u32(pBh);
    const uint32_t sBl = smem_u32(pBl);

    const int tid  = threadIdx.x;
    const int wid  = tid >> 5;
    const int lane = tid & 31;
    const int wm   = wid >> 1;           // 0..3
    const int wn   = wid & 1;            // 0..1
    const int bm   = blockIdx.y * 128;
    const int bn   = blockIdx.x * 128;

    float acc[2][8][4];
#pragma unroll
    for (int mt = 0; mt < 2; ++mt)
#pragma unroll
        for (int nt = 0; nt < 8; ++nt)
#pragma unroll
            for (int j = 0; j < 4; ++j) acc[mt][nt][j] = 0.f;

    float4 ra[8];
    uint4  rbh[4], rbl[4];

    // prologue: chunk 0
    ldg_chunk(A, Bh, Bl, bm, bn, 0, tid, ra, rbh, rbl);
    sts_chunk(pAh, pAl, pBh, pBl, tid, ra, rbh, rbl);
    __syncthreads();

    for (int ch = 0; ch < DD / KC; ++ch) {
        if (ch + 1 < DD / KC)
            ldg_chunk(A, Bh, Bl, bm, bn, (ch + 1) * KC, tid, ra, rbh, rbl);
        compute_chunk(sAh, sAl, sBh, sBl, wm, wn, lane, acc);
        __syncthreads();
        if (ch + 1 < DD / KC) {
            sts_chunk(pAh, pAl, pBh, pBl, tid, ra, rbh, rbl);
            __syncthreads();
        }
    }

    // epilogue
#pragma unroll
    for (int mt = 0; mt < 2; ++mt)
#pragma unroll
        for (int nt = 0; nt < 8; ++nt) {
            int row = bm + wm * 32 + mt * 16 + (lane >> 2);
            int col = bn + wn * 64 + nt * 8 + (lane & 3) * 2;
            float2 v0 = make_float2(acc[mt][nt][0], acc[mt][nt][1]);
            float2 v1 = make_float2(acc[mt][nt][2], acc[mt][nt][3]);
            if (PHI) {
                v0.x = (v0.x > 0.f) ? (v0.x + 1.f) : expf(v0.x);
                v0.y = (v0.y > 0.f) ? (v0.y + 1.f) : expf(v0.y);
                v1.x = (v1.x > 0.f) ? (v1.x + 1.f) : expf(v1.x);
                v1.y = (v1.y > 0.f) ? (v1.y + 1.f) : expf(v1.y);
            }
            *(float2*)(C + (size_t)row * DD + col)       = v0;
            *(float2*)(C + (size_t)(row + 8) * DD + col) = v1;
        }
}

// ---------- Kv = sum_l Kf[l,:]^T V[l,:]  and K1 = sum_l Kf[l,:] -----------
__global__ __launch_bounds__(256)
void kv_part_k() {
    const int bh    = blockIdx.x;
    const int split = blockIdx.y;
    const int b = bh >> 4, h = bh & 15;

    __shared__ float Ks[32][64];
    __shared__ float Vs[32][64];

    const int tid = threadIdx.x;
    const int tx  = tid & 15;
    const int ty  = tid >> 4;

    float acc[4][4];
#pragma unroll
    for (int i = 0; i < 4; ++i)
#pragma unroll
        for (int j = 0; j < 4; ++j) acc[i][j] = 0.f;
    float k1a[4] = {0.f, 0.f, 0.f, 0.f};

    const size_t base = ((size_t)b * LL) * DD + (size_t)h * DH;
    const int l0 = split * LCHUNK;

    for (int lt = 0; lt < LCHUNK; lt += 32) {
#pragma unroll
        for (int t = 0; t < 2; ++t) {
            int v = tid + t * 256;
            int r = v >> 4;
            int c = (v & 15) << 2;
            size_t g = base + (size_t)(l0 + lt + r) * DD + c;
            *(float4*)&Ks[r][c] = *(const float4*)(g_Kf + g);
            *(float4*)&Vs[r][c] = *(const float4*)(g_V  + g);
        }
        __syncthreads();
#pragma unroll 8
        for (int r = 0; r < 32; ++r) {
            float a0 = Ks[r][ty * 4 + 0], a1 = Ks[r][ty * 4 + 1];
            float a2 = Ks[r][ty * 4 + 2], a3 = Ks[r][ty * 4 + 3];
            float b0 = Vs[r][tx * 4 + 0], b1 = Vs[r][tx * 4 + 1];
            float b2 = Vs[r][tx * 4 + 2], b3 = Vs[r][tx * 4 + 3];
            acc[0][0] = fmaf(a0, b0, acc[0][0]); acc[0][1] = fmaf(a0, b1, acc[0][1]);
            acc[0][2] = fmaf(a0, b2, acc[0][2]); acc[0][3] = fmaf(a0, b3, acc[0][3]);
            acc[1][0] = fmaf(a1, b0, acc[1][0]); acc[1][1] = fmaf(a1, b1, acc[1][1]);
            acc[1][2] = fmaf(a1, b2, acc[1][2]); acc[1][3] = fmaf(a1, b3, acc[1][3]);
            acc[2][0] = fmaf(a2, b0, acc[2][0]); acc[2][1] = fmaf(a2, b1, acc[2][1]);
            acc[2][2] = fmaf(a2, b2, acc[2][2]); acc[2][3] = fmaf(a2, b3, acc[2][3]);
            acc[3][0] = fmaf(a3, b0, acc[3][0]); acc[3][1] = fmaf(a3, b1, acc[3][1]);
            acc[3][2] = fmaf(a3, b2, acc[3][2]); acc[3][3] = fmaf(a3, b3, acc[3][3]);
            k1a[0] += a0; k1a[1] += a1; k1a[2] += a2; k1a[3] += a3;
        }
        __syncthreads();
    }

    float* kp = g_KvPart + ((size_t)bh * SPLITS + split) * (DH * DH);
#pragma unroll
    for (int i = 0; i < 4; ++i)
#pragma unroll
        for (int j = 0; j < 4; ++j)
            kp[(ty * 4 + i) * DH + tx * 4 + j] = acc[i][j];
    if (tx == 0) {
        float* k1p = g_K1Part + ((size_t)bh * SPLITS + split) * DH;
#pragma unroll
        for (int i = 0; i < 4; ++i) k1p[ty * 4 + i] = k1a[i];
    }
}

__global__ __launch_bounds__(256)
void kv_reduce_k() {
    const int bh  = blockIdx.x;
    const int tid = threadIdx.x;
    for (int idx = tid; idx < DH * DH; idx += 256) {
        float s = 0.f;
#pragma unroll
        for (int sp = 0; sp < SPLITS; ++sp)
            s += g_KvPart[((size_t)bh * SPLITS + sp) * (DH * DH) + idx];
        g_Kv[(size_t)bh * (DH * DH) + idx] = s;
    }
    if (tid < DH) {
        float s = 0.f;
#pragma unroll
        for (int sp = 0; sp < SPLITS; ++sp)
            s += g_K1Part[((size_t)bh * SPLITS + sp) * DH + tid];
        g_K1[bh * DH + tid] = s;
    }
}

__global__ __launch_bounds__(256)
void numden_k() {
    const int bh = blockIdx.x;
    const int lt = blockIdx.y;
    const int b = bh >> 4, h = bh & 15;

    __shared__ float Kvs[64][64];
    __shared__ float Qs[64][64];
    __shared__ float K1s[64];

    const int tid = threadIdx.x;
    const int tx  = tid & 15;
    const int ty  = tid >> 4;

    const size_t base = ((size_t)b * LL + (size_t)lt * 64) * DD + (size_t)h * DH;

    {
        const float4* src = (const float4*)(g_Kv + (size_t)bh * DH * DH);
        float4* dst = (float4*)&Kvs[0][0];
#pragma unroll
        for (int t = 0; t < 4; ++t) dst[tid + t * 256] = src[tid + t * 256];
    }
#pragma unroll
    for (int t = 0; t < 4; ++t) {
        int v = tid + t * 256;
        int r = v >> 4, c = (v & 15) << 2;
        *(float4*)&Qs[r][c] = *(const float4*)(g_Qf + base + (size_t)r * DD + c);
    }
    if (tid < DH) K1s[tid] = g_K1[bh * DH + tid];
    __syncthreads();

    float acc[4][4];
#pragma unroll
    for (int i = 0; i < 4; ++i)
#pragma unroll
        for (int j = 0; j < 4; ++j) acc[i][j] = 0.f;
    float den[4] = {0.f, 0.f, 0.f, 0.f};
#pragma unroll 8
    for (int m = 0; m < 64; ++m) {
        float k1m = K1s[m];
        float a0 = Qs[ty * 4 + 0][m], a1 = Qs[ty * 4 + 1][m];
        float a2 = Qs[ty * 4 + 2][m], a3 = Qs[ty * 4 + 3][m];
        float b0 = Kvs[m][tx * 4 + 0], b1 = Kvs[m][tx * 4 + 1];
        float b2 = Kvs[m][tx * 4 + 2], b3 = Kvs[m][tx * 4 + 3];
        acc[0][0] = fmaf(a0, b0, acc[0][0]); acc[0][1] = fmaf(a0, b1, acc[0][1]);
        acc[0][2] = fmaf(a0, b2, acc[0][2]); acc[0][3] = fmaf(a0, b3, acc[0][3]);
        acc[1][0] = fmaf(a1, b0, acc[1][0]); acc[1][1] = fmaf(a1, b1, acc[1][1]);
        acc[1][2] = fmaf(a1, b2, acc[1][2]); acc[1][3] = fmaf(a1, b3, acc[1][3]);
        acc[2][0] = fmaf(a2, b0, acc[2][0]); acc[2][1] = fmaf(a2, b1, acc[2][1]);
        acc[2][2] = fmaf(a2, b2, acc[2][2]); acc[2][3] = fmaf(a2, b3, acc[2][3]);
        acc[3][0] = fmaf(a3, b0, acc[3][0]); acc[3][1] = fmaf(a3, b1, acc[3][1]);
        acc[3][2] = fmaf(a3, b2, acc[3][2]); acc[3][3] = fmaf(a3, b3, acc[3][3]);
        den[0] = fmaf(a0, k1m, den[0]); den[1] = fmaf(a1, k1m, den[1]);
        den[2] = fmaf(a2, k1m, den[2]); den[3] = fmaf(a3, k1m, den[3]);
    }

#pragma unroll
    for (int i = 0; i < 4; ++i) {
        int r = ty * 4 + i;
        float inv = 1.f / (den[i] + EPSV);
        float4 o;
        o.x = acc[i][0] * inv; o.y = acc[i][1] * inv;
        o.z = acc[i][2] * inv; o.w = acc[i][3] * inv;
        *(float4*)(g_att + base + (size_t)r * DD + tx * 4) = o;
    }
}

// --------------------------- host launch --------------------------------
extern "C" void kernel_launch(void* const* d_in, const int* in_sizes, int n_in,
                              void* d_out, int out_size) {
    const float* x  = (const float*)d_in[0];
    const float* Wq = (const float*)d_in[1];
    const float* Wk = (const float*)d_in[2];
    const float* Wv = (const float*)d_in[3];
    const float* Wo = (const float*)d_in[4];
    float* out = (float*)d_out;

    float *qf, *kf, *v, *att;
    __nv_bfloat16 *wth, *wtl;
    cudaGetSymbolAddress((void**)&qf,  g_Qf);
    cudaGetSymbolAddress((void**)&kf,  g_Kf);
    cudaGetSymbolAddress((void**)&v,   g_V);
    cudaGetSymbolAddress((void**)&att, g_att);
    cudaGetSymbolAddress((void**)&wth, g_Wth);
    cudaGetSymbolAddress((void**)&wtl, g_Wtl);

    cudaFuncSetAttribute(mma_gemm_k<0>,
                         cudaFuncAttributeMaxDynamicSharedMemorySize, GEMM_SMEM);
    cudaFuncSetAttribute(mma_gemm_k<1>,
                         cudaFuncAttributeMaxDynamicSharedMemorySize, GEMM_SMEM);

    // pre-pass: transpose+split the four weight matrices
    dim3 wg(DD / 32, DD / 32);
    wsplit_k<<<wg, 256>>>(Wq, wth + 0 * DD * DD, wtl + 0 * DD * DD);
    wsplit_k<<<wg, 256>>>(Wk, wth + 1 * DD * DD, wtl + 1 * DD * DD);
    wsplit_k<<<wg, 256>>>(Wv, wth + 2 * DD * DD, wtl + 2 * DD * DD);
    wsplit_k<<<wg, 256>>>(Wo, wth + 3 * DD * DD, wtl + 3 * DD * DD);

    dim3 gg(DD / 128, MLROWS / 128);          // (8, 256)
    mma_gemm_k<1><<<gg, 256, GEMM_SMEM>>>(x, wth + 0 * DD * DD, wtl + 0 * DD * DD, qf);
    mma_gemm_k<1><<<gg, 256, GEMM_SMEM>>>(x, wth + 1 * DD * DD, wtl + 1 * DD * DD, kf);
    mma_gemm_k<0><<<gg, 256, GEMM_SMEM>>>(x, wth + 2 * DD * DD, wtl + 2 * DD * DD, v);

    kv_part_k<<<dim3(BB * HH, SPLITS), 256>>>();
    kv_reduce_k<<<BB * HH, 256>>>();
    numden_k<<<dim3(BB * HH, LL / 64), 256>>>();

    mma_gemm_k<0><<<gg, 256, GEMM_SMEM>>>(att, wth + 3 * DD * DD, wtl + 3 * DD * DD, out);
}

// round 6
// speedup vs baseline: 2.9707x; 1.2958x over previous
#include <cuda_runtime.h>
#include <cuda_bf16.h>
#include <stdint.h>
#include <math.h>

#define BB     4
#define LL     8192
#define DD     1024
#define HH     16
#define DH     64
#define MLROWS (BB * LL)          // 32768
#define NQKV   (3 * DD)           // 3072
#define EPSV   1e-6f
#define SPLITS 16
#define LCHUNK (LL / SPLITS)      // 512

// GEMM tiling: CTA 128x128, 8 warps (4x2), warp tile 32x64, K-chunk 64
#define KC 64
#define STAGE_BYTES (64 * 1024)
#define GEMM_SMEM   (2 * STAGE_BYTES)

// ---------------- scratch (static device globals; no allocation) ----------
__device__ float g_QKV[(size_t)MLROWS * NQKV];          // Qf | Kf | V  (stride 3072)
__device__ __nv_bfloat16 g_Xh[(size_t)MLROWS * DD];
__device__ __nv_bfloat16 g_Xl[(size_t)MLROWS * DD];
__device__ __nv_bfloat16 g_attH[(size_t)MLROWS * DD];
__device__ __nv_bfloat16 g_attL[(size_t)MLROWS * DD];
__device__ float g_KvPart[BB * HH * SPLITS * DH * DH];
__device__ float g_K1Part[BB * HH * SPLITS * DH];
__device__ float g_Kv[BB * HH * DH * DH];
__device__ float g_K1[BB * HH * DH];
__device__ __nv_bfloat16 g_Wth[4][DD * DD];             // [N,K] hi (Wq|Wk|Wv|Wo)
__device__ __nv_bfloat16 g_Wtl[4][DD * DD];             // [N,K] lo

// =========================== helpers ==================================
__device__ __forceinline__ uint32_t smem_u32(const void* p) {
    return (uint32_t)__cvta_generic_to_shared(p);
}

__device__ __forceinline__ void split2(float a, float b, uint32_t& hw, uint32_t& lw) {
    __nv_bfloat16 ha = __float2bfloat16(a);
    __nv_bfloat16 hb = __float2bfloat16(b);
    __nv_bfloat16 la = __float2bfloat16(a - __bfloat162float(ha));
    __nv_bfloat16 lb = __float2bfloat16(b - __bfloat162float(hb));
    hw = (uint32_t)__bfloat16_as_ushort(ha) | ((uint32_t)__bfloat16_as_ushort(hb) << 16);
    lw = (uint32_t)__bfloat16_as_ushort(la) | ((uint32_t)__bfloat16_as_ushort(lb) << 16);
}

#define LDSM_X4(r0, r1, r2, r3, addr) \
    asm volatile("ldmatrix.sync.aligned.m8n8.x4.shared.b16 {%0,%1,%2,%3}, [%4];" \
                 : "=r"(r0), "=r"(r1), "=r"(r2), "=r"(r3) : "r"(addr))

#define MMA16816(d, a, b0, b1) \
    asm volatile("mma.sync.aligned.m16n8k16.row.col.f32.bf16.bf16.f32 " \
                 "{%0,%1,%2,%3}, {%4,%5,%6,%7}, {%8,%9}, {%0,%1,%2,%3};" \
                 : "+f"((d)[0]), "+f"((d)[1]), "+f"((d)[2]), "+f"((d)[3]) \
                 : "r"((a)[0]), "r"((a)[1]), "r"((a)[2]), "r"((a)[3]), \
                   "r"(b0), "r"(b1))

__device__ __forceinline__ void cp16(uint32_t dst, const void* src) {
    asm volatile("cp.async.cg.shared.global [%0], [%1], 16;"
                 :: "r"(dst), "l"(src));
}
#define CP_COMMIT() asm volatile("cp.async.commit_group;" ::: "memory")
#define CP_WAIT(n)  asm volatile("cp.async.wait_group %0;" :: "n"(n) : "memory")

// ================= pre-pass: x fp32 -> hi/lo bf16 =========================
__global__ __launch_bounds__(256)
void xsplit_k(const float* __restrict__ X,
              __nv_bfloat16* __restrict__ H, __nv_bfloat16* __restrict__ L) {
    size_t i = ((size_t)blockIdx.x * 256 + threadIdx.x) * 4;
    float4 v = *(const float4*)(X + i);
    uint32_t h0, l0, h1, l1;
    split2(v.x, v.y, h0, l0);
    split2(v.z, v.w, h1, l1);
    *(uint2*)(H + i) = make_uint2(h0, h1);
    *(uint2*)(L + i) = make_uint2(l0, l1);
}

// ================= weight pre-pass: W[K,N] -> Wt_hi/lo[N,K] bf16 ==========
__global__ __launch_bounds__(256)
void wsplit_k(const float* __restrict__ W,
              __nv_bfloat16* __restrict__ Th,
              __nv_bfloat16* __restrict__ Tl) {
    __shared__ float t[32][33];
    const int nb = blockIdx.x * 32;
    const int kb = blockIdx.y * 32;
    const int tx = threadIdx.x & 31;
    const int ty = threadIdx.x >> 5;
    for (int i = ty; i < 32; i += 8)
        t[i][tx] = W[(size_t)(kb + i) * DD + nb + tx];
    __syncthreads();
    for (int i = ty; i < 32; i += 8) {
        float v = t[tx][i];
        __nv_bfloat16 h = __float2bfloat16(v);
        __nv_bfloat16 l = __float2bfloat16(v - __bfloat162float(h));
        size_t o = (size_t)(nb + i) * DD + kb + tx;
        Th[o] = h; Tl[o] = l;
    }
}

// ================= mma.sync bf16 GEMM (all-bf16, cp.async pipelined) ======
// C[M,Ncols] = A[M,K] * W[K,Ncols]; A given hi/lo [M,K]; W hi/lo [Ncols,K].
// 3-term split: Ah*Wh + Al*Wh + Ah*Wl, fp32 accumulate.

__device__ __forceinline__ void cpa_chunk(
    uint32_t sb,
    const __nv_bfloat16* __restrict__ Ah, const __nv_bfloat16* __restrict__ Al,
    const __nv_bfloat16* __restrict__ Bh, const __nv_bfloat16* __restrict__ Bl,
    int bm, int bn, int k0, int tid) {
#pragma unroll
    for (int t = 0; t < 4; ++t) {
        int idx = tid + t * 256;             // 0..1023
        int row = idx >> 3;                  // 0..127
        int cb  = (idx & 7) << 4;            // 0..112 bytes
        uint32_t off = (uint32_t)(row * 128 + cb);
        uint32_t sw  = off ^ ((off >> 3) & 0x70);
        const char* gAh = (const char*)(Ah + (size_t)(bm + row) * DD + k0) + cb;
        const char* gAl = (const char*)(Al + (size_t)(bm + row) * DD + k0) + cb;
        const char* gBh = (const char*)(Bh + (size_t)(bn + row) * DD + k0) + cb;
        const char* gBl = (const char*)(Bl + (size_t)(bn + row) * DD + k0) + cb;
        cp16(sb + sw,                 gAh);
        cp16(sb + 16384 + sw,         gAl);
        cp16(sb + 32768 + sw,         gBh);
        cp16(sb + 49152 + sw,         gBl);
    }
}

__device__ __forceinline__ void compute_chunk(
    uint32_t sb, int wm, int wn, int lane, float acc[2][8][4]) {
    const uint32_t sAh = sb, sAl = sb + 16384, sBh = sb + 32768, sBl = sb + 49152;
    const int i   = lane & 7;
    const int sub = lane >> 3;
#pragma unroll
    for (int ks = 0; ks < 4; ++ks) {
        uint32_t ah[2][4], al[2][4], bh[8][2], bl[8][2];
#pragma unroll
        for (int mt = 0; mt < 2; ++mt) {
            int row = wm * 32 + mt * 16 + i + ((sub & 1) << 3);
            int kk  = ks * 16 + ((sub & 2) << 2);
            uint32_t off = (uint32_t)(row * 128 + kk * 2);
            uint32_t sw  = off ^ ((off >> 3) & 0x70);
            LDSM_X4(ah[mt][0], ah[mt][1], ah[mt][2], ah[mt][3], sAh + sw);
            LDSM_X4(al[mt][0], al[mt][1], al[mt][2], al[mt][3], sAl + sw);
        }
#pragma unroll
        for (int np = 0; np < 4; ++np) {
            int row = wn * 64 + np * 16 + i + ((sub & 2) << 2);
            int kk  = ks * 16 + ((sub & 1) << 3);
            uint32_t off = (uint32_t)(row * 128 + kk * 2);
            uint32_t sw  = off ^ ((off >> 3) & 0x70);
            uint32_t r0, r1, r2, r3;
            LDSM_X4(r0, r1, r2, r3, sBh + sw);
            bh[2 * np][0] = r0; bh[2 * np][1] = r1;
            bh[2 * np + 1][0] = r2; bh[2 * np + 1][1] = r3;
            LDSM_X4(r0, r1, r2, r3, sBl + sw);
            bl[2 * np][0] = r0; bl[2 * np][1] = r1;
            bl[2 * np + 1][0] = r2; bl[2 * np + 1][1] = r3;
        }
#pragma unroll
        for (int mt = 0; mt < 2; ++mt)
#pragma unroll
            for (int nt = 0; nt < 8; ++nt) {
                MMA16816(acc[mt][nt], ah[mt], bh[nt][0], bh[nt][1]);
                MMA16816(acc[mt][nt], al[mt], bh[nt][0], bh[nt][1]);
                MMA16816(acc[mt][nt], ah[mt], bl[nt][0], bl[nt][1]);
            }
    }
}

__global__ __launch_bounds__(256)
void mma_gemm_k(const __nv_bfloat16* __restrict__ Ah,
                const __nv_bfloat16* __restrict__ Al,
                const __nv_bfloat16* __restrict__ Bh,
                const __nv_bfloat16* __restrict__ Bl,
                float* __restrict__ C, int Ncols, int phiLimit) {
    extern __shared__ char sm[];
    const uint32_t s0 = smem_u32(sm);

    const int tid  = threadIdx.x;
    const int wid  = tid >> 5;
    const int lane = tid & 31;
    const int wm   = wid >> 1;
    const int wn   = wid & 1;
    const int bm   = blockIdx.y * 128;
    const int bn   = blockIdx.x * 128;
    const bool phi = bn < phiLimit;

    float acc[2][8][4];
#pragma unroll
    for (int mt = 0; mt < 2; ++mt)
#pragma unroll
        for (int nt = 0; nt < 8; ++nt)
#pragma unroll
            for (int j = 0; j < 4; ++j) acc[mt][nt][j] = 0.f;

    cpa_chunk(s0, Ah, Al, Bh, Bl, bm, bn, 0, tid);
    CP_COMMIT();

    for (int ch = 0; ch < DD / KC; ++ch) {
        if (ch + 1 < DD / KC) {
            cpa_chunk(s0 + ((uint32_t)((ch + 1) & 1)) * STAGE_BYTES,
                      Ah, Al, Bh, Bl, bm, bn, (ch + 1) * KC, tid);
            CP_COMMIT();
            CP_WAIT(1);
        } else {
            CP_WAIT(0);
        }
        __syncthreads();
        compute_chunk(s0 + ((uint32_t)(ch & 1)) * STAGE_BYTES, wm, wn, lane, acc);
        __syncthreads();
    }

    // epilogue
#pragma unroll
    for (int mt = 0; mt < 2; ++mt)
#pragma unroll
        for (int nt = 0; nt < 8; ++nt) {
            int row = bm + wm * 32 + mt * 16 + (lane >> 2);
            int col = bn + wn * 64 + nt * 8 + (lane & 3) * 2;
            float2 v0 = make_float2(acc[mt][nt][0], acc[mt][nt][1]);
            float2 v1 = make_float2(acc[mt][nt][2], acc[mt][nt][3]);
            if (phi) {
                v0.x = (v0.x > 0.f) ? (v0.x + 1.f) : expf(v0.x);
                v0.y = (v0.y > 0.f) ? (v0.y + 1.f) : expf(v0.y);
                v1.x = (v1.x > 0.f) ? (v1.x + 1.f) : expf(v1.x);
                v1.y = (v1.y > 0.f) ? (v1.y + 1.f) : expf(v1.y);
            }
            *(float2*)(C + (size_t)row * Ncols + col)       = v0;
            *(float2*)(C + (size_t)(row + 8) * Ncols + col) = v1;
        }
}

// ---------- Kv = sum_l Kf^T V  and K1 = sum_l Kf (from g_QKV) -------------
__global__ __launch_bounds__(256)
void kv_part_k() {
    const int bh    = blockIdx.x;
    const int split = blockIdx.y;
    const int b = bh >> 4, h = bh & 15;

    __shared__ float Ks[32][64];
    __shared__ float Vs[32][64];

    const int tid = threadIdx.x;
    const int tx  = tid & 15;
    const int ty  = tid >> 4;

    float acc[4][4];
#pragma unroll
    for (int i = 0; i < 4; ++i)
#pragma unroll
        for (int j = 0; j < 4; ++j) acc[i][j] = 0.f;
    float k1a[4] = {0.f, 0.f, 0.f, 0.f};

    // K block starts at col DD, V block at col 2*DD, row stride NQKV
    const size_t baseK = ((size_t)b * LL) * NQKV + DD + (size_t)h * DH;
    const int l0 = split * LCHUNK;

    for (int lt = 0; lt < LCHUNK; lt += 32) {
#pragma unroll
        for (int t = 0; t < 2; ++t) {
            int v = tid + t * 256;
            int r = v >> 4;
            int c = (v & 15) << 2;
            size_t g = baseK + (size_t)(l0 + lt + r) * NQKV + c;
            *(float4*)&Ks[r][c] = *(const float4*)(g_QKV + g);
            *(float4*)&Vs[r][c] = *(const float4*)(g_QKV + g + DD);
        }
        __syncthreads();
#pragma unroll 8
        for (int r = 0; r < 32; ++r) {
            float a0 = Ks[r][ty * 4 + 0], a1 = Ks[r][ty * 4 + 1];
            float a2 = Ks[r][ty * 4 + 2], a3 = Ks[r][ty * 4 + 3];
            float b0 = Vs[r][tx * 4 + 0], b1 = Vs[r][tx * 4 + 1];
            float b2 = Vs[r][tx * 4 + 2], b3 = Vs[r][tx * 4 + 3];
            acc[0][0] = fmaf(a0, b0, acc[0][0]); acc[0][1] = fmaf(a0, b1, acc[0][1]);
            acc[0][2] = fmaf(a0, b2, acc[0][2]); acc[0][3] = fmaf(a0, b3, acc[0][3]);
            acc[1][0] = fmaf(a1, b0, acc[1][0]); acc[1][1] = fmaf(a1, b1, acc[1][1]);
            acc[1][2] = fmaf(a1, b2, acc[1][2]); acc[1][3] = fmaf(a1, b3, acc[1][3]);
            acc[2][0] = fmaf(a2, b0, acc[2][0]); acc[2][1] = fmaf(a2, b1, acc[2][1]);
            acc[2][2] = fmaf(a2, b2, acc[2][2]); acc[2][3] = fmaf(a2, b3, acc[2][3]);
            acc[3][0] = fmaf(a3, b0, acc[3][0]); acc[3][1] = fmaf(a3, b1, acc[3][1]);
            acc[3][2] = fmaf(a3, b2, acc[3][2]); acc[3][3] = fmaf(a3, b3, acc[3][3]);
            k1a[0] += a0; k1a[1] += a1; k1a[2] += a2; k1a[3] += a3;
        }
        __syncthreads();
    }

    float* kp = g_KvPart + ((size_t)bh * SPLITS + split) * (DH * DH);
#pragma unroll
    for (int i = 0; i < 4; ++i)
#pragma unroll
        for (int j = 0; j < 4; ++j)
            kp[(ty * 4 + i) * DH + tx * 4 + j] = acc[i][j];
    if (tx == 0) {
        float* k1p = g_K1Part + ((size_t)bh * SPLITS + split) * DH;
#pragma unroll
        for (int i = 0; i < 4; ++i) k1p[ty * 4 + i] = k1a[i];
    }
}

__global__ __launch_bounds__(256)
void kv_reduce_k() {
    const int bh  = blockIdx.x;
    const int tid = threadIdx.x;
    for (int idx = tid; idx < DH * DH; idx += 256) {
        float s = 0.f;
#pragma unroll
        for (int sp = 0; sp < SPLITS; ++sp)
            s += g_KvPart[((size_t)bh * SPLITS + sp) * (DH * DH) + idx];
        g_Kv[(size_t)bh * (DH * DH) + idx] = s;
    }
    if (tid < DH) {
        float s = 0.f;
#pragma unroll
        for (int sp = 0; sp < SPLITS; ++sp)
            s += g_K1Part[((size_t)bh * SPLITS + sp) * DH + tid];
        g_K1[bh * DH + tid] = s;
    }
}

// att = (Qf @ Kv) / (Qf @ K1 + eps), written directly as bf16 hi/lo
__global__ __launch_bounds__(256)
void numden_k() {
    const int bh = blockIdx.x;
    const int lt = blockIdx.y;
    const int b = bh >> 4, h = bh & 15;

    __shared__ float Kvs[64][64];
    __shared__ float Qs[64][64];
    __shared__ float K1s[64];

    const int tid = threadIdx.x;
    const int tx  = tid & 15;
    const int ty  = tid >> 4;

    const size_t baseQ = ((size_t)b * LL + (size_t)lt * 64) * NQKV + (size_t)h * DH;
    const size_t baseO = ((size_t)b * LL + (size_t)lt * 64) * DD   + (size_t)h * DH;

    {
        const float4* src = (const float4*)(g_Kv + (size_t)bh * DH * DH);
        float4* dst = (float4*)&Kvs[0][0];
#pragma unroll
        for (int t = 0; t < 4; ++t) dst[tid + t * 256] = src[tid + t * 256];
    }
#pragma unroll
    for (int t = 0; t < 4; ++t) {
        int v = tid + t * 256;
        int r = v >> 4, c = (v & 15) << 2;
        *(float4*)&Qs[r][c] = *(const float4*)(g_QKV + baseQ + (size_t)r * NQKV + c);
    }
    if (tid < DH) K1s[tid] = g_K1[bh * DH + tid];
    __syncthreads();

    float acc[4][4];
#pragma unroll
    for (int i = 0; i < 4; ++i)
#pragma unroll
        for (int j = 0; j < 4; ++j) acc[i][j] = 0.f;
    float den[4] = {0.f, 0.f, 0.f, 0.f};
#pragma unroll 8
    for (int m = 0; m < 64; ++m) {
        float k1m = K1s[m];
        float a0 = Qs[ty * 4 + 0][m], a1 = Qs[ty * 4 + 1][m];
        float a2 = Qs[ty * 4 + 2][m], a3 = Qs[ty * 4 + 3][m];
        float b0 = Kvs[m][tx * 4 + 0], b1 = Kvs[m][tx * 4 + 1];
        float b2 = Kvs[m][tx * 4 + 2], b3 = Kvs[m][tx * 4 + 3];
        acc[0][0] = fmaf(a0, b0, acc[0][0]); acc[0][1] = fmaf(a0, b1, acc[0][1]);
        acc[0][2] = fmaf(a0, b2, acc[0][2]); acc[0][3] = fmaf(a0, b3, acc[0][3]);
        acc[1][0] = fmaf(a1, b0, acc[1][0]); acc[1][1] = fmaf(a1, b1, acc[1][1]);
        acc[1][2] = fmaf(a1, b2, acc[1][2]); acc[1][3] = fmaf(a1, b3, acc[1][3]);
        acc[2][0] = fmaf(a2, b0, acc[2][0]); acc[2][1] = fmaf(a2, b1, acc[2][1]);
        acc[2][2] = fmaf(a2, b2, acc[2][2]); acc[2][3] = fmaf(a2, b3, acc[2][3]);
        acc[3][0] = fmaf(a3, b0, acc[3][0]); acc[3][1] = fmaf(a3, b1, acc[3][1]);
        acc[3][2] = fmaf(a3, b2, acc[3][2]); acc[3][3] = fmaf(a3, b3, acc[3][3]);
        den[0] = fmaf(a0, k1m, den[0]); den[1] = fmaf(a1, k1m, den[1]);
        den[2] = fmaf(a2, k1m, den[2]); den[3] = fmaf(a3, k1m, den[3]);
    }

#pragma unroll
    for (int i = 0; i < 4; ++i) {
        int r = ty * 4 + i;
        float inv = 1.f / (den[i] + EPSV);
        float4 o;
        o.x = acc[i][0] * inv; o.y = acc[i][1] * inv;
        o.z = acc[i][2] * inv; o.w = acc[i][3] * inv;
        uint32_t h0, l0, h1, l1;
        split2(o.x, o.y, h0, l0);
        split2(o.z, o.w, h1, l1);
        size_t idx = baseO + (size_t)r * DD + tx * 4;
        *(uint2*)(g_attH + idx) = make_uint2(h0, h1);
        *(uint2*)(g_attL + idx) = make_uint2(l0, l1);
    }
}

// --------------------------- host launch --------------------------------
extern "C" void kernel_launch(void* const* d_in, const int* in_sizes, int n_in,
                              void* d_out, int out_size) {
    const float* x  = (const float*)d_in[0];
    const float* Wq = (const float*)d_in[1];
    const float* Wk = (const float*)d_in[2];
    const float* Wv = (const float*)d_in[3];
    const float* Wo = (const float*)d_in[4];
    float* out = (float*)d_out;

    float* qkv;
    __nv_bfloat16 *xh, *xl, *ath, *atl, *wth, *wtl;
    cudaGetSymbolAddress((void**)&qkv, g_QKV);
    cudaGetSymbolAddress((void**)&xh,  g_Xh);
    cudaGetSymbolAddress((void**)&xl,  g_Xl);
    cudaGetSymbolAddress((void**)&ath, g_attH);
    cudaGetSymbolAddress((void**)&atl, g_attL);
    cudaGetSymbolAddress((void**)&wth, g_Wth);
    cudaGetSymbolAddress((void**)&wtl, g_Wtl);

    cudaFuncSetAttribute(mma_gemm_k,
                         cudaFuncAttributeMaxDynamicSharedMemorySize, GEMM_SMEM);

    // pre-passes
    xsplit_k<<<MLROWS * DD / 1024, 256>>>(x, xh, xl);
    dim3 wg(DD / 32, DD / 32);
    wsplit_k<<<wg, 256>>>(Wq, wth + 0 * (size_t)DD * DD, wtl + 0 * (size_t)DD * DD);
    wsplit_k<<<wg, 256>>>(Wk, wth + 1 * (size_t)DD * DD, wtl + 1 * (size_t)DD * DD);
    wsplit_k<<<wg, 256>>>(Wv, wth + 2 * (size_t)DD * DD, wtl + 2 * (size_t)DD * DD);
    wsplit_k<<<wg, 256>>>(Wo, wth + 3 * (size_t)DD * DD, wtl + 3 * (size_t)DD * DD);

    // fused QKV GEMM: N = 3072, phi on cols < 2048 (Q and K blocks)
    dim3 gqkv(NQKV / 128, MLROWS / 128);      // (24, 256)
    mma_gemm_k<<<gqkv, 256, GEMM_SMEM>>>(xh, xl, wth, wtl, qkv, NQKV, 2 * DD);

    kv_part_k<<<dim3(BB * HH, SPLITS), 256>>>();
    kv_reduce_k<<<BB * HH, 256>>>();
    numden_k<<<dim3(BB * HH, LL / 64), 256>>>();

    // output GEMM: N = 1024, no phi
    dim3 gout(DD / 128, MLROWS / 128);        // (8, 256)
    mma_gemm_k<<<gout, 256, GEMM_SMEM>>>(ath, atl,
                                         wth + 3 * (size_t)DD * DD,
                                         wtl + 3 * (size_t)DD * DD,
                                         out, DD, 0);
}

// round 7
// speedup vs baseline: 3.0782x; 1.0362x over previous
#include <cuda_runtime.h>
#include <cuda_bf16.h>
#include <stdint.h>
#include <math.h>

#define BB     4
#define LL     8192
#define DD     1024
#define HH     16
#define DH     64
#define MLROWS (BB * LL)          // 32768
#define NQKV   (3 * DD)           // 3072
#define EPSV   1e-6f
#define SPLITS 16
#define LCHUNK (LL / SPLITS)      // 512

// GEMM tiling: CTA 128x256, 16 warps (4x4), warp tile 32x64, K-chunk 64
#define KC 64
#define GTHREADS 512
#define STAGE_BYTES 98304          // A hi/lo 16K+16K, B hi/lo 32K+32K
#define GEMM_SMEM   (2 * STAGE_BYTES)

// ---------------- scratch (static device globals; no allocation) ----------
__device__ float g_QKV[(size_t)MLROWS * NQKV];          // Qf | Kf | V  (stride 3072)
__device__ __nv_bfloat16 g_Xh[(size_t)MLROWS * DD];
__device__ __nv_bfloat16 g_Xl[(size_t)MLROWS * DD];
__device__ __nv_bfloat16 g_attH[(size_t)MLROWS * DD];
__device__ __nv_bfloat16 g_attL[(size_t)MLROWS * DD];
__device__ float g_KvPart[BB * HH * SPLITS * DH * DH];
__device__ float g_K1Part[BB * HH * SPLITS * DH];
__device__ float g_Kv[BB * HH * DH * DH];
__device__ float g_K1[BB * HH * DH];
__device__ __nv_bfloat16 g_Wth[4][DD * DD];             // [N,K] hi (Wq|Wk|Wv|Wo)
__device__ __nv_bfloat16 g_Wtl[4][DD * DD];             // [N,K] lo

// =========================== helpers ==================================
__device__ __forceinline__ uint32_t smem_u32(const void* p) {
    return (uint32_t)__cvta_generic_to_shared(p);
}

__device__ __forceinline__ void split2(float a, float b, uint32_t& hw, uint32_t& lw) {
    __nv_bfloat16 ha = __float2bfloat16(a);
    __nv_bfloat16 hb = __float2bfloat16(b);
    __nv_bfloat16 la = __float2bfloat16(a - __bfloat162float(ha));
    __nv_bfloat16 lb = __float2bfloat16(b - __bfloat162float(hb));
    hw = (uint32_t)__bfloat16_as_ushort(ha) | ((uint32_t)__bfloat16_as_ushort(hb) << 16);
    lw = (uint32_t)__bfloat16_as_ushort(la) | ((uint32_t)__bfloat16_as_ushort(lb) << 16);
}

#define LDSM_X4(r0, r1, r2, r3, addr) \
    asm volatile("ldmatrix.sync.aligned.m8n8.x4.shared.b16 {%0,%1,%2,%3}, [%4];" \
                 : "=r"(r0), "=r"(r1), "=r"(r2), "=r"(r3) : "r"(addr))

#define MMA16816(d, a, b0, b1) \
    asm volatile("mma.sync.aligned.m16n8k16.row.col.f32.bf16.bf16.f32 " \
                 "{%0,%1,%2,%3}, {%4,%5,%6,%7}, {%8,%9}, {%0,%1,%2,%3};" \
                 : "+f"((d)[0]), "+f"((d)[1]), "+f"((d)[2]), "+f"((d)[3]) \
                 : "r"((a)[0]), "r"((a)[1]), "r"((a)[2]), "r"((a)[3]), \
                   "r"(b0), "r"(b1))

__device__ __forceinline__ void cp16(uint32_t dst, const void* src) {
    asm volatile("cp.async.cg.shared.global [%0], [%1], 16;"
                 :: "r"(dst), "l"(src));
}
#define CP_COMMIT() asm volatile("cp.async.commit_group;" ::: "memory")
#define CP_WAIT(n)  asm volatile("cp.async.wait_group %0;" :: "n"(n) : "memory")

// ================= pre-pass: x fp32 -> hi/lo bf16 =========================
__global__ __launch_bounds__(256)
void xsplit_k(const float* __restrict__ X,
              __nv_bfloat16* __restrict__ H, __nv_bfloat16* __restrict__ L) {
    size_t i = ((size_t)blockIdx.x * 256 + threadIdx.x) * 4;
    float4 v = *(const float4*)(X + i);
    uint32_t h0, l0, h1, l1;
    split2(v.x, v.y, h0, l0);
    split2(v.z, v.w, h1, l1);
    *(uint2*)(H + i) = make_uint2(h0, h1);
    *(uint2*)(L + i) = make_uint2(l0, l1);
}

// ================= weight pre-pass: W[K,N] -> Wt_hi/lo[N,K] bf16 ==========
__global__ __launch_bounds__(256)
void wsplit_k(const float* __restrict__ W,
              __nv_bfloat16* __restrict__ Th,
              __nv_bfloat16* __restrict__ Tl) {
    __shared__ float t[32][33];
    const int nb = blockIdx.x * 32;
    const int kb = blockIdx.y * 32;
    const int tx = threadIdx.x & 31;
    const int ty = threadIdx.x >> 5;
    for (int i = ty; i < 32; i += 8)
        t[i][tx] = W[(size_t)(kb + i) * DD + nb + tx];
    __syncthreads();
    for (int i = ty; i < 32; i += 8) {
        float v = t[tx][i];
        __nv_bfloat16 h = __float2bfloat16(v);
        __nv_bfloat16 l = __float2bfloat16(v - __bfloat162float(h));
        size_t o = (size_t)(nb + i) * DD + kb + tx;
        Th[o] = h; Tl[o] = l;
    }
}

// ================= mma.sync bf16 GEMM (all-bf16, cp.async pipelined) ======
// C[M,Ncols] = A[M,K] * W[K,Ncols]; A hi/lo [M,K]; W hi/lo [Ncols,K].
// 3-term split: Ah*Wh + Al*Wh + Ah*Wl, fp32 accumulate.
// Stage layout: A_hi @0 (16K), A_lo @16K, B_hi @32K (32K), B_lo @64K (32K).

__device__ __forceinline__ void cpa_chunk(
    uint32_t sb,
    const __nv_bfloat16* __restrict__ Ah, const __nv_bfloat16* __restrict__ Al,
    const __nv_bfloat16* __restrict__ Bh, const __nv_bfloat16* __restrict__ Bl,
    int bm, int bn, int k0, int tid) {
#pragma unroll
    for (int t = 0; t < 2; ++t) {            // A: 128 rows x 8 uint4
        int idx = tid + t * GTHREADS;        // 0..1023
        int row = idx >> 3;                  // 0..127
        int cb  = (idx & 7) << 4;            // 0..112 bytes
        uint32_t off = (uint32_t)(row * 128 + cb);
        uint32_t sw  = off ^ ((off >> 3) & 0x70);
        cp16(sb + sw,         (const char*)(Ah + (size_t)(bm + row) * DD + k0) + cb);
        cp16(sb + 16384 + sw, (const char*)(Al + (size_t)(bm + row) * DD + k0) + cb);
    }
#pragma unroll
    for (int t = 0; t < 4; ++t) {            // B: 256 rows x 8 uint4
        int idx = tid + t * GTHREADS;        // 0..2047
        int row = idx >> 3;                  // 0..255
        int cb  = (idx & 7) << 4;
        uint32_t off = (uint32_t)(row * 128 + cb);
        uint32_t sw  = off ^ ((off >> 3) & 0x70);
        cp16(sb + 32768 + sw, (const char*)(Bh + (size_t)(bn + row) * DD + k0) + cb);
        cp16(sb + 65536 + sw, (const char*)(Bl + (size_t)(bn + row) * DD + k0) + cb);
    }
}

__device__ __forceinline__ void compute_chunk(
    uint32_t sb, int wm, int wn, int lane, float acc[2][8][4]) {
    const uint32_t sAh = sb, sAl = sb + 16384, sBh = sb + 32768, sBl = sb + 65536;
    const int i   = lane & 7;
    const int sub = lane >> 3;
#pragma unroll
    for (int ks = 0; ks < 4; ++ks) {
        uint32_t ah[2][4], al[2][4], bh[8][2], bl[8][2];
#pragma unroll
        for (int mt = 0; mt < 2; ++mt) {
            int row = wm * 32 + mt * 16 + i + ((sub & 1) << 3);
            int kk  = ks * 16 + ((sub & 2) << 2);
            uint32_t off = (uint32_t)(row * 128 + kk * 2);
            uint32_t sw  = off ^ ((off >> 3) & 0x70);
            LDSM_X4(ah[mt][0], ah[mt][1], ah[mt][2], ah[mt][3], sAh + sw);
            LDSM_X4(al[mt][0], al[mt][1], al[mt][2], al[mt][3], sAl + sw);
        }
#pragma unroll
        for (int np = 0; np < 4; ++np) {
            int row = wn * 64 + np * 16 + i + ((sub & 2) << 2);
            int kk  = ks * 16 + ((sub & 1) << 3);
            uint32_t off = (uint32_t)(row * 128 + kk * 2);
            uint32_t sw  = off ^ ((off >> 3) & 0x70);
            uint32_t r0, r1, r2, r3;
            LDSM_X4(r0, r1, r2, r3, sBh + sw);
            bh[2 * np][0] = r0; bh[2 * np][1] = r1;
            bh[2 * np + 1][0] = r2; bh[2 * np + 1][1] = r3;
            LDSM_X4(r0, r1, r2, r3, sBl + sw);
            bl[2 * np][0] = r0; bl[2 * np][1] = r1;
            bl[2 * np + 1][0] = r2; bl[2 * np + 1][1] = r3;
        }
#pragma unroll
        for (int mt = 0; mt < 2; ++mt)
#pragma unroll
            for (int nt = 0; nt < 8; ++nt) {
                MMA16816(acc[mt][nt], ah[mt], bh[nt][0], bh[nt][1]);
                MMA16816(acc[mt][nt], al[mt], bh[nt][0], bh[nt][1]);
                MMA16816(acc[mt][nt], ah[mt], bl[nt][0], bl[nt][1]);
            }
    }
}

__global__ __launch_bounds__(GTHREADS, 1)
void mma_gemm_k(const __nv_bfloat16* __restrict__ Ah,
                const __nv_bfloat16* __restrict__ Al,
                const __nv_bfloat16* __restrict__ Bh,
                const __nv_bfloat16* __restrict__ Bl,
                float* __restrict__ C, int Ncols, int phiLimit) {
    extern __shared__ char sm[];
    const uint32_t s0 = smem_u32(sm);

    const int tid  = threadIdx.x;
    const int wid  = tid >> 5;
    const int lane = tid & 31;
    const int wm   = wid >> 2;           // 0..3
    const int wn   = wid & 3;            // 0..3
    const int bm   = blockIdx.y * 128;
    const int bn   = blockIdx.x * 256;
    const bool phi = bn < phiLimit;

    float acc[2][8][4];
#pragma unroll
    for (int mt = 0; mt < 2; ++mt)
#pragma unroll
        for (int nt = 0; nt < 8; ++nt)
#pragma unroll
            for (int j = 0; j < 4; ++j) acc[mt][nt][j] = 0.f;

    cpa_chunk(s0, Ah, Al, Bh, Bl, bm, bn, 0, tid);
    CP_COMMIT();

    for (int ch = 0; ch < DD / KC; ++ch) {
        if (ch + 1 < DD / KC) {
            cpa_chunk(s0 + ((uint32_t)((ch + 1) & 1)) * STAGE_BYTES,
                      Ah, Al, Bh, Bl, bm, bn, (ch + 1) * KC, tid);
            CP_COMMIT();
            CP_WAIT(1);
        } else {
            CP_WAIT(0);
        }
        __syncthreads();
        compute_chunk(s0 + ((uint32_t)(ch & 1)) * STAGE_BYTES, wm, wn, lane, acc);
        __syncthreads();
    }

    // epilogue
#pragma unroll
    for (int mt = 0; mt < 2; ++mt)
#pragma unroll
        for (int nt = 0; nt < 8; ++nt) {
            int row = bm + wm * 32 + mt * 16 + (lane >> 2);
            int col = bn + wn * 64 + nt * 8 + (lane & 3) * 2;
            float2 v0 = make_float2(acc[mt][nt][0], acc[mt][nt][1]);
            float2 v1 = make_float2(acc[mt][nt][2], acc[mt][nt][3]);
            if (phi) {
                v0.x = (v0.x > 0.f) ? (v0.x + 1.f) : expf(v0.x);
                v0.y = (v0.y > 0.f) ? (v0.y + 1.f) : expf(v0.y);
                v1.x = (v1.x > 0.f) ? (v1.x + 1.f) : expf(v1.x);
                v1.y = (v1.y > 0.f) ? (v1.y + 1.f) : expf(v1.y);
            }
            *(float2*)(C + (size_t)row * Ncols + col)       = v0;
            *(float2*)(C + (size_t)(row + 8) * Ncols + col) = v1;
        }
}

// ---------- Kv = sum_l Kf^T V  and K1 = sum_l Kf (from g_QKV) -------------
__global__ __launch_bounds__(256)
void kv_part_k() {
    const int bh    = blockIdx.x;
    const int split = blockIdx.y;
    const int b = bh >> 4, h = bh & 15;

    __shared__ float Ks[32][64];
    __shared__ float Vs[32][64];

    const int tid = threadIdx.x;
    const int tx  = tid & 15;
    const int ty  = tid >> 4;

    float acc[4][4];
#pragma unroll
    for (int i = 0; i < 4; ++i)
#pragma unroll
        for (int j = 0; j < 4; ++j) acc[i][j] = 0.f;
    float k1a[4] = {0.f, 0.f, 0.f, 0.f};

    const size_t baseK = ((size_t)b * LL) * NQKV + DD + (size_t)h * DH;
    const int l0 = split * LCHUNK;

    for (int lt = 0; lt < LCHUNK; lt += 32) {
#pragma unroll
        for (int t = 0; t < 2; ++t) {
            int v = tid + t * 256;
            int r = v >> 4;
            int c = (v & 15) << 2;
            size_t g = baseK + (size_t)(l0 + lt + r) * NQKV + c;
            *(float4*)&Ks[r][c] = *(const float4*)(g_QKV + g);
            *(float4*)&Vs[r][c] = *(const float4*)(g_QKV + g + DD);
        }
        __syncthreads();
#pragma unroll 8
        for (int r = 0; r < 32; ++r) {
            float a0 = Ks[r][ty * 4 + 0], a1 = Ks[r][ty * 4 + 1];
            float a2 = Ks[r][ty * 4 + 2], a3 = Ks[r][ty * 4 + 3];
            float b0 = Vs[r][tx * 4 + 0], b1 = Vs[r][tx * 4 + 1];
            float b2 = Vs[r][tx * 4 + 2], b3 = Vs[r][tx * 4 + 3];
            acc[0][0] = fmaf(a0, b0, acc[0][0]); acc[0][1] = fmaf(a0, b1, acc[0][1]);
            acc[0][2] = fmaf(a0, b2, acc[0][2]); acc[0][3] = fmaf(a0, b3, acc[0][3]);
            acc[1][0] = fmaf(a1, b0, acc[1][0]); acc[1][1] = fmaf(a1, b1, acc[1][1]);
            acc[1][2] = fmaf(a1, b2, acc[1][2]); acc[1][3] = fmaf(a1, b3, acc[1][3]);
            acc[2][0] = fmaf(a2, b0, acc[2][0]); acc[2][1] = fmaf(a2, b1, acc[2][1]);
            acc[2][2] = fmaf(a2, b2, acc[2][2]); acc[2][3] = fmaf(a2, b3, acc[2][3]);
            acc[3][0] = fmaf(a3, b0, acc[3][0]); acc[3][1] = fmaf(a3, b1, acc[3][1]);
            acc[3][2] = fmaf(a3, b2, acc[3][2]); acc[3][3] = fmaf(a3, b3, acc[3][3]);
            k1a[0] += a0; k1a[1] += a1; k1a[2] += a2; k1a[3] += a3;
        }
        __syncthreads();
    }

    float* kp = g_KvPart + ((size_t)bh * SPLITS + split) * (DH * DH);
#pragma unroll
    for (int i = 0; i < 4; ++i)
#pragma unroll
        for (int j = 0; j < 4; ++j)
            kp[(ty * 4 + i) * DH + tx * 4 + j] = acc[i][j];
    if (tx == 0) {
        float* k1p = g_K1Part + ((size_t)bh * SPLITS + split) * DH;
#pragma unroll
        for (int i = 0; i < 4; ++i) k1p[ty * 4 + i] = k1a[i];
    }
}

__global__ __launch_bounds__(256)
void kv_reduce_k() {
    const int bh  = blockIdx.x;
    const int tid = threadIdx.x;
    for (int idx = tid; idx < DH * DH; idx += 256) {
        float s = 0.f;
#pragma unroll
        for (int sp = 0; sp < SPLITS; ++sp)
            s += g_KvPart[((size_t)bh * SPLITS + sp) * (DH * DH) + idx];
        g_Kv[(size_t)bh * (DH * DH) + idx] = s;
    }
    if (tid < DH) {
        float s = 0.f;
#pragma unroll
        for (int sp = 0; sp < SPLITS; ++sp)
            s += g_K1Part[((size_t)bh * SPLITS + sp) * DH + tid];
        g_K1[bh * DH + tid] = s;
    }
}

// att = (Qf @ Kv) / (Qf @ K1 + eps), written directly as bf16 hi/lo
__global__ __launch_bounds__(256)
void numden_k() {
    const int bh = blockIdx.x;
    const int lt = blockIdx.y;
    const int b = bh >> 4, h = bh & 15;

    __shared__ float Kvs[64][64];
    __shared__ float Qs[64][64];
    __shared__ float K1s[64];

    const int tid = threadIdx.x;
    const int tx  = tid & 15;
    const int ty  = tid >> 4;

    const size_t baseQ = ((size_t)b * LL + (size_t)lt * 64) * NQKV + (size_t)h * DH;
    const size_t baseO = ((size_t)b * LL + (size_t)lt * 64) * DD   + (size_t)h * DH;

    {
        const float4* src = (const float4*)(g_Kv + (size_t)bh * DH * DH);
        float4* dst = (float4*)&Kvs[0][0];
#pragma unroll
        for (int t = 0; t < 4; ++t) dst[tid + t * 256] = src[tid + t * 256];
    }
#pragma unroll
    for (int t = 0; t < 4; ++t) {
        int v = tid + t * 256;
        int r = v >> 4, c = (v & 15) << 2;
        *(float4*)&Qs[r][c] = *(const float4*)(g_QKV + baseQ + (size_t)r * NQKV + c);
    }
    if (tid < DH) K1s[tid] = g_K1[bh * DH + tid];
    __syncthreads();

    float acc[4][4];
#pragma unroll
    for (int i = 0; i < 4; ++i)
#pragma unroll
        for (int j = 0; j < 4; ++j) acc[i][j] = 0.f;
    float den[4] = {0.f, 0.f, 0.f, 0.f};
#pragma unroll 8
    for (int m = 0; m < 64; ++m) {
        float k1m = K1s[m];
        float a0 = Qs[ty * 4 + 0][m], a1 = Qs[ty * 4 + 1][m];
        float a2 = Qs[ty * 4 + 2][m], a3 = Qs[ty * 4 + 3][m];
        float b0 = Kvs[m][tx * 4 + 0], b1 = Kvs[m][tx * 4 + 1];
        float b2 = Kvs[m][tx * 4 + 2], b3 = Kvs[m][tx * 4 + 3];
        acc[0][0] = fmaf(a0, b0, acc[0][0]); acc[0][1] = fmaf(a0, b1, acc[0][1]);
        acc[0][2] = fmaf(a0, b2, acc[0][2]); acc[0][3] = fmaf(a0, b3, acc[0][3]);
        acc[1][0] = fmaf(a1, b0, acc[1][0]); acc[1][1] = fmaf(a1, b1, acc[1][1]);
        acc[1][2] = fmaf(a1, b2, acc[1][2]); acc[1][3] = fmaf(a1, b3, acc[1][3]);
        acc[2][0] = fmaf(a2, b0, acc[2][0]); acc[2][1] = fmaf(a2, b1, acc[2][1]);
        acc[2][2] = fmaf(a2, b2, acc[2][2]); acc[2][3] = fmaf(a2, b3, acc[2][3]);
        acc[3][0] = fmaf(a3, b0, acc[3][0]); acc[3][1] = fmaf(a3, b1, acc[3][1]);
        acc[3][2] = fmaf(a3, b2, acc[3][2]); acc[3][3] = fmaf(a3, b3, acc[3][3]);
        den[0] = fmaf(a0, k1m, den[0]); den[1] = fmaf(a1, k1m, den[1]);
        den[2] = fmaf(a2, k1m, den[2]); den[3] = fmaf(a3, k1m, den[3]);
    }

#pragma unroll
    for (int i = 0; i < 4; ++i) {
        int r = ty * 4 + i;
        float inv = 1.f / (den[i] + EPSV);
        float4 o;
        o.x = acc[i][0] * inv; o.y = acc[i][1] * inv;
        o.z = acc[i][2] * inv; o.w = acc[i][3] * inv;
        uint32_t h0, l0, h1, l1;
        split2(o.x, o.y, h0, l0);
        split2(o.z, o.w, h1, l1);
        size_t idx = baseO + (size_t)r * DD + tx * 4;
        *(uint2*)(g_attH + idx) = make_uint2(h0, h1);
        *(uint2*)(g_attL + idx) = make_uint2(l0, l1);
    }
}

// --------------------------- host launch --------------------------------
extern "C" void kernel_launch(void* const* d_in, const int* in_sizes, int n_in,
                              void* d_out, int out_size) {
    const float* x  = (const float*)d_in[0];
    const float* Wq = (const float*)d_in[1];
    const float* Wk = (const float*)d_in[2];
    const float* Wv = (const float*)d_in[3];
    const float* Wo = (const float*)d_in[4];
    float* out = (float*)d_out;

    float* qkv;
    __nv_bfloat16 *xh, *xl, *ath, *atl, *wth, *wtl;
    cudaGetSymbolAddress((void**)&qkv, g_QKV);
    cudaGetSymbolAddress((void**)&xh,  g_Xh);
    cudaGetSymbolAddress((void**)&xl,  g_Xl);
    cudaGetSymbolAddress((void**)&ath, g_attH);
    cudaGetSymbolAddress((void**)&atl, g_attL);
    cudaGetSymbolAddress((void**)&wth, g_Wth);
    cudaGetSymbolAddress((void**)&wtl, g_Wtl);

    cudaFuncSetAttribute(mma_gemm_k,
                         cudaFuncAttributeMaxDynamicSharedMemorySize, GEMM_SMEM);

    // pre-passes
    xsplit_k<<<MLROWS * DD / 1024, 256>>>(x, xh, xl);
    dim3 wg(DD / 32, DD / 32);
    wsplit_k<<<wg, 256>>>(Wq, wth + 0 * (size_t)DD * DD, wtl + 0 * (size_t)DD * DD);
    wsplit_k<<<wg, 256>>>(Wk, wth + 1 * (size_t)DD * DD, wtl + 1 * (size_t)DD * DD);
    wsplit_k<<<wg, 256>>>(Wv, wth + 2 * (size_t)DD * DD, wtl + 2 * (size_t)DD * DD);
    wsplit_k<<<wg, 256>>>(Wo, wth + 3 * (size_t)DD * DD, wtl + 3 * (size_t)DD * DD);

    // fused QKV GEMM: N = 3072, phi on cols < 2048 (Q and K blocks)
    dim3 gqkv(NQKV / 256, MLROWS / 128);      // (12, 256)
    mma_gemm_k<<<gqkv, GTHREADS, GEMM_SMEM>>>(xh, xl, wth, wtl, qkv, NQKV, 2 * DD);

    kv_part_k<<<dim3(BB * HH, SPLITS), 256>>>();
    kv_reduce_k<<<BB * HH, 256>>>();
    numden_k<<<dim3(BB * HH, LL / 64), 256>>>();

    // output GEMM: N = 1024, no phi
    dim3 gout(DD / 256, MLROWS / 128);        // (4, 256)
    mma_gemm_k<<<gout, GTHREADS, GEMM_SMEM>>>(ath, atl,
                                              wth + 3 * (size_t)DD * DD,
                                              wtl + 3 * (size_t)DD * DD,
                                              out, DD, 0);
}

// round 8
// speedup vs baseline: 4.1514x; 1.3486x over previous
#include <cuda_runtime.h>
#include <cuda_fp16.h>
#include <stdint.h>
#include <math.h>

#define BB     4
#define LL     8192
#define DD     1024
#define HH     16
#define DH     64
#define MLROWS (BB * LL)          // 32768
#define NQKV   (3 * DD)           // 3072
#define EPSV   1e-6f
#define SPLITS 16
#define LCHUNK (LL / SPLITS)      // 512

// GEMM tiling: CTA 128x256, 16 warps (4x4), warp tile 32x64, K-chunk 64
#define KC 64
#define GTHREADS 512
#define STAGE_BYTES 65536          // A hi/lo 16K+16K, B 32K
#define GEMM_SMEM   (2 * STAGE_BYTES)

// ---------------- scratch (static device globals; no allocation) ----------
__device__ float g_QKV[(size_t)MLROWS * NQKV];          // Qf | Kf | V  (stride 3072)
__device__ __half g_Xh[(size_t)MLROWS * DD];
__device__ __half g_Xl[(size_t)MLROWS * DD];
__device__ __half g_attH[(size_t)MLROWS * DD];
__device__ __half g_attL[(size_t)MLROWS * DD];
__device__ float g_KvPart[BB * HH * SPLITS * DH * DH];
__device__ float g_K1Part[BB * HH * SPLITS * DH];
__device__ float g_Kv[BB * HH * DH * DH];
__device__ float g_K1[BB * HH * DH];
__device__ __half g_Wt[4][DD * DD];                     // [N,K] fp16 (Wq|Wk|Wv|Wo)

// =========================== helpers ==================================
__device__ __forceinline__ uint32_t smem_u32(const void* p) {
    return (uint32_t)__cvta_generic_to_shared(p);
}

__device__ __forceinline__ void split2h(float a, float b, uint32_t& hw, uint32_t& lw) {
    __half ha = __float2half_rn(a);
    __half hb = __float2half_rn(b);
    __half la = __float2half_rn(a - __half2float(ha));
    __half lb = __float2half_rn(b - __half2float(hb));
    hw = (uint32_t)__half_as_ushort(ha) | ((uint32_t)__half_as_ushort(hb) << 16);
    lw = (uint32_t)__half_as_ushort(la) | ((uint32_t)__half_as_ushort(lb) << 16);
}

#define LDSM_X4(r0, r1, r2, r3, addr) \
    asm volatile("ldmatrix.sync.aligned.m8n8.x4.shared.b16 {%0,%1,%2,%3}, [%4];" \
                 : "=r"(r0), "=r"(r1), "=r"(r2), "=r"(r3) : "r"(addr))

#define MMA16816H(d, a, b0, b1) \
    asm volatile("mma.sync.aligned.m16n8k16.row.col.f32.f16.f16.f32 " \
                 "{%0,%1,%2,%3}, {%4,%5,%6,%7}, {%8,%9}, {%0,%1,%2,%3};" \
                 : "+f"((d)[0]), "+f"((d)[1]), "+f"((d)[2]), "+f"((d)[3]) \
                 : "r"((a)[0]), "r"((a)[1]), "r"((a)[2]), "r"((a)[3]), \
                   "r"(b0), "r"(b1))

__device__ __forceinline__ void cp16(uint32_t dst, const void* src) {
    asm volatile("cp.async.cg.shared.global [%0], [%1], 16;"
                 :: "r"(dst), "l"(src));
}
#define CP_COMMIT() asm volatile("cp.async.commit_group;" ::: "memory")
#define CP_WAIT(n)  asm volatile("cp.async.wait_group %0;" :: "n"(n) : "memory")

// ================= pre-pass: x fp32 -> hi/lo fp16 =========================
__global__ __launch_bounds__(256)
void xsplit_k(const float* __restrict__ X,
              __half* __restrict__ H, __half* __restrict__ L) {
    size_t i = ((size_t)blockIdx.x * 256 + threadIdx.x) * 4;
    float4 v = *(const float4*)(X + i);
    uint32_t h0, l0, h1, l1;
    split2h(v.x, v.y, h0, l0);
    split2h(v.z, v.w, h1, l1);
    *(uint2*)(H + i) = make_uint2(h0, h1);
    *(uint2*)(L + i) = make_uint2(l0, l1);
}

// ================= weight pre-pass: W[K,N] -> Wt[N,K] fp16 ================
__global__ __launch_bounds__(256)
void wsplit_k(const float* __restrict__ W, __half* __restrict__ T) {
    __shared__ float t[32][33];
    const int nb = blockIdx.x * 32;
    const int kb = blockIdx.y * 32;
    const int tx = threadIdx.x & 31;
    const int ty = threadIdx.x >> 5;
    for (int i = ty; i < 32; i += 8)
        t[i][tx] = W[(size_t)(kb + i) * DD + nb + tx];
    __syncthreads();
    for (int i = ty; i < 32; i += 8) {
        size_t o = (size_t)(nb + i) * DD + kb + tx;
        T[o] = __float2half_rn(t[tx][i]);
    }
}

// ================= mma.sync fp16 GEMM (2-term, cp.async pipelined) ========
// C[M,Ncols] = A[M,K] * W[K,Ncols]; A hi/lo fp16 [M,K]; W fp16 [Ncols,K].
// C = Ah*W + Al*W, fp32 accumulate.
// Stage layout: A_hi @0 (16K), A_lo @16K, B @32K (32K).

__device__ __forceinline__ void cpa_chunk(
    uint32_t sb,
    const __half* __restrict__ Ah, const __half* __restrict__ Al,
    const __half* __restrict__ B,
    int bm, int bn, int k0, int tid) {
#pragma unroll
    for (int t = 0; t < 2; ++t) {            // A: 128 rows x 8 uint4
        int idx = tid + t * GTHREADS;        // 0..1023
        int row = idx >> 3;                  // 0..127
        int cb  = (idx & 7) << 4;            // 0..112 bytes
        uint32_t off = (uint32_t)(row * 128 + cb);
        uint32_t sw  = off ^ ((off >> 3) & 0x70);
        cp16(sb + sw,         (const char*)(Ah + (size_t)(bm + row) * DD + k0) + cb);
        cp16(sb + 16384 + sw, (const char*)(Al + (size_t)(bm + row) * DD + k0) + cb);
    }
#pragma unroll
    for (int t = 0; t < 4; ++t) {            // B: 256 rows x 8 uint4
        int idx = tid + t * GTHREADS;        // 0..2047
        int row = idx >> 3;                  // 0..255
        int cb  = (idx & 7) << 4;
        uint32_t off = (uint32_t)(row * 128 + cb);
        uint32_t sw  = off ^ ((off >> 3) & 0x70);
        cp16(sb + 32768 + sw, (const char*)(B + (size_t)(bn + row) * DD + k0) + cb);
    }
}

__device__ __forceinline__ void compute_chunk(
    uint32_t sb, int wm, int wn, int lane, float acc[2][8][4]) {
    const uint32_t sAh = sb, sAl = sb + 16384, sB = sb + 32768;
    const int i   = lane & 7;
    const int sub = lane >> 3;
#pragma unroll
    for (int ks = 0; ks < 4; ++ks) {
        uint32_t ah[2][4], al[2][4], b[8][2];
#pragma unroll
        for (int mt = 0; mt < 2; ++mt) {
            int row = wm * 32 + mt * 16 + i + ((sub & 1) << 3);
            int kk  = ks * 16 + ((sub & 2) << 2);
            uint32_t off = (uint32_t)(row * 128 + kk * 2);
            uint32_t sw  = off ^ ((off >> 3) & 0x70);
            LDSM_X4(ah[mt][0], ah[mt][1], ah[mt][2], ah[mt][3], sAh + sw);
            LDSM_X4(al[mt][0], al[mt][1], al[mt][2], al[mt][3], sAl + sw);
        }
#pragma unroll
        for (int np = 0; np < 4; ++np) {
            int row = wn * 64 + np * 16 + i + ((sub & 2) << 2);
            int kk  = ks * 16 + ((sub & 1) << 3);
            uint32_t off = (uint32_t)(row * 128 + kk * 2);
            uint32_t sw  = off ^ ((off >> 3) & 0x70);
            uint32_t r0, r1, r2, r3;
            LDSM_X4(r0, r1, r2, r3, sB + sw);
            b[2 * np][0] = r0; b[2 * np][1] = r1;
            b[2 * np + 1][0] = r2; b[2 * np + 1][1] = r3;
        }
#pragma unroll
        for (int mt = 0; mt < 2; ++mt)
#pragma unroll
            for (int nt = 0; nt < 8; ++nt) {
                MMA16816H(acc[mt][nt], ah[mt], b[nt][0], b[nt][1]);
                MMA16816H(acc[mt][nt], al[mt], b[nt][0], b[nt][1]);
            }
    }
}

__global__ __launch_bounds__(GTHREADS, 1)
void mma_gemm_k(const __half* __restrict__ Ah,
                const __half* __restrict__ Al,
                const __half* __restrict__ B,
                float* __restrict__ C, int Ncols, int phiLimit) {
    extern __shared__ char sm[];
    const uint32_t s0 = smem_u32(sm);

    const int tid  = threadIdx.x;
    const int wid  = tid >> 5;
    const int lane = tid & 31;
    const int wm   = wid >> 2;           // 0..3
    const int wn   = wid & 3;            // 0..3
    const int bm   = blockIdx.y * 128;
    const int bn   = blockIdx.x * 256;
    const bool phi = bn < phiLimit;

    float acc[2][8][4];
#pragma unroll
    for (int mt = 0; mt < 2; ++mt)
#pragma unroll
        for (int nt = 0; nt < 8; ++nt)
#pragma unroll
            for (int j = 0; j < 4; ++j) acc[mt][nt][j] = 0.f;

    cpa_chunk(s0, Ah, Al, B, bm, bn, 0, tid);
    CP_COMMIT();

    for (int ch = 0; ch < DD / KC; ++ch) {
        if (ch + 1 < DD / KC) {
            cpa_chunk(s0 + ((uint32_t)((ch + 1) & 1)) * STAGE_BYTES,
                      Ah, Al, B, bm, bn, (ch + 1) * KC, tid);
            CP_COMMIT();
            CP_WAIT(1);
        } else {
            CP_WAIT(0);
        }
        __syncthreads();
        compute_chunk(s0 + ((uint32_t)(ch & 1)) * STAGE_BYTES, wm, wn, lane, acc);
        __syncthreads();
    }

    // epilogue
#pragma unroll
    for (int mt = 0; mt < 2; ++mt)
#pragma unroll
        for (int nt = 0; nt < 8; ++nt) {
            int row = bm + wm * 32 + mt * 16 + (lane >> 2);
            int col = bn + wn * 64 + nt * 8 + (lane & 3) * 2;
            float2 v0 = make_float2(acc[mt][nt][0], acc[mt][nt][1]);
            float2 v1 = make_float2(acc[mt][nt][2], acc[mt][nt][3]);
            if (phi) {
                v0.x = (v0.x > 0.f) ? (v0.x + 1.f) : expf(v0.x);
                v0.y = (v0.y > 0.f) ? (v0.y + 1.f) : expf(v0.y);
                v1.x = (v1.x > 0.f) ? (v1.x + 1.f) : expf(v1.x);
                v1.y = (v1.y > 0.f) ? (v1.y + 1.f) : expf(v1.y);
            }
            *(float2*)(C + (size_t)row * Ncols + col)       = v0;
            *(float2*)(C + (size_t)(row + 8) * Ncols + col) = v1;
        }
}

// ---------- Kv = sum_l Kf^T V  and K1 = sum_l Kf (from g_QKV) -------------
__global__ __launch_bounds__(256)
void kv_part_k() {
    const int bh    = blockIdx.x;
    const int split = blockIdx.y;
    const int b = bh >> 4, h = bh & 15;

    __shared__ float Ks[32][64];
    __shared__ float Vs[32][64];

    const int tid = threadIdx.x;
    const int tx  = tid & 15;
    const int ty  = tid >> 4;

    float acc[4][4];
#pragma unroll
    for (int i = 0; i < 4; ++i)
#pragma unroll
        for (int j = 0; j < 4; ++j) acc[i][j] = 0.f;
    float k1a[4] = {0.f, 0.f, 0.f, 0.f};

    const size_t baseK = ((size_t)b * LL) * NQKV + DD + (size_t)h * DH;
    const int l0 = split * LCHUNK;

    for (int lt = 0; lt < LCHUNK; lt += 32) {
#pragma unroll
        for (int t = 0; t < 2; ++t) {
            int v = tid + t * 256;
            int r = v >> 4;
            int c = (v & 15) << 2;
            size_t g = baseK + (size_t)(l0 + lt + r) * NQKV + c;
            *(float4*)&Ks[r][c] = *(const float4*)(g_QKV + g);
            *(float4*)&Vs[r][c] = *(const float4*)(g_QKV + g + DD);
        }
        __syncthreads();
#pragma unroll 8
        for (int r = 0; r < 32; ++r) {
            float a0 = Ks[r][ty * 4 + 0], a1 = Ks[r][ty * 4 + 1];
            float a2 = Ks[r][ty * 4 + 2], a3 = Ks[r][ty * 4 + 3];
            float b0 = Vs[r][tx * 4 + 0], b1 = Vs[r][tx * 4 + 1];
            float b2 = Vs[r][tx * 4 + 2], b3 = Vs[r][tx * 4 + 3];
            acc[0][0] = fmaf(a0, b0, acc[0][0]); acc[0][1] = fmaf(a0, b1, acc[0][1]);
            acc[0][2] = fmaf(a0, b2, acc[0][2]); acc[0][3] = fmaf(a0, b3, acc[0][3]);
            acc[1][0] = fmaf(a1, b0, acc[1][0]); acc[1][1] = fmaf(a1, b1, acc[1][1]);
            acc[1][2] = fmaf(a1, b2, acc[1][2]); acc[1][3] = fmaf(a1, b3, acc[1][3]);
            acc[2][0] = fmaf(a2, b0, acc[2][0]); acc[2][1] = fmaf(a2, b1, acc[2][1]);
            acc[2][2] = fmaf(a2, b2, acc[2][2]); acc[2][3] = fmaf(a2, b3, acc[2][3]);
            acc[3][0] = fmaf(a3, b0, acc[3][0]); acc[3][1] = fmaf(a3, b1, acc[3][1]);
            acc[3][2] = fmaf(a3, b2, acc[3][2]); acc[3][3] = fmaf(a3, b3, acc[3][3]);
            k1a[0] += a0; k1a[1] += a1; k1a[2] += a2; k1a[3] += a3;
        }
        __syncthreads();
    }

    float* kp = g_KvPart + ((size_t)bh * SPLITS + split) * (DH * DH);
#pragma unroll
    for (int i = 0; i < 4; ++i)
#pragma unroll
        for (int j = 0; j < 4; ++j)
            kp[(ty * 4 + i) * DH + tx * 4 + j] = acc[i][j];
    if (tx == 0) {
        float* k1p = g_K1Part + ((size_t)bh * SPLITS + split) * DH;
#pragma unroll
        for (int i = 0; i < 4; ++i) k1p[ty * 4 + i] = k1a[i];
    }
}

__global__ __launch_bounds__(256)
void kv_reduce_k() {
    const int bh  = blockIdx.x;
    const int tid = threadIdx.x;
    for (int idx = tid; idx < DH * DH; idx += 256) {
        float s = 0.f;
#pragma unroll
        for (int sp = 0; sp < SPLITS; ++sp)
            s += g_KvPart[((size_t)bh * SPLITS + sp) * (DH * DH) + idx];
        g_Kv[(size_t)bh * (DH * DH) + idx] = s;
    }
    if (tid < DH) {
        float s = 0.f;
#pragma unroll
        for (int sp = 0; sp < SPLITS; ++sp)
            s += g_K1Part[((size_t)bh * SPLITS + sp) * DH + tid];
        g_K1[bh * DH + tid] = s;
    }
}

// att = (Qf @ Kv) / (Qf @ K1 + eps), written directly as fp16 hi/lo
__global__ __launch_bounds__(256)
void numden_k() {
    const int bh = blockIdx.x;
    const int lt = blockIdx.y;
    const int b = bh >> 4, h = bh & 15;

    __shared__ float Kvs[64][64];
    __shared__ float Qs[64][64];
    __shared__ float K1s[64];

    const int tid = threadIdx.x;
    const int tx  = tid & 15;
    const int ty  = tid >> 4;

    const size_t baseQ = ((size_t)b * LL + (size_t)lt * 64) * NQKV + (size_t)h * DH;
    const size_t baseO = ((size_t)b * LL + (size_t)lt * 64) * DD   + (size_t)h * DH;

    {
        const float4* src = (const float4*)(g_Kv + (size_t)bh * DH * DH);
        float4* dst = (float4*)&Kvs[0][0];
#pragma unroll
        for (int t = 0; t < 4; ++t) dst[tid + t * 256] = src[tid + t * 256];
    }
#pragma unroll
    for (int t = 0; t < 4; ++t) {
        int v = tid + t * 256;
        int r = v >> 4, c = (v & 15) << 2;
        *(float4*)&Qs[r][c] = *(const float4*)(g_QKV + baseQ + (size_t)r * NQKV + c);
    }
    if (tid < DH) K1s[tid] = g_K1[bh * DH + tid];
    __syncthreads();

    float acc[4][4];
#pragma unroll
    for (int i = 0; i < 4; ++i)
#pragma unroll
        for (int j = 0; j < 4; ++j) acc[i][j] = 0.f;
    float den[4] = {0.f, 0.f, 0.f, 0.f};
#pragma unroll 8
    for (int m = 0; m < 64; ++m) {
        float k1m = K1s[m];
        float a0 = Qs[ty * 4 + 0][m], a1 = Qs[ty * 4 + 1][m];
        float a2 = Qs[ty * 4 + 2][m], a3 = Qs[ty * 4 + 3][m];
        float b0 = Kvs[m][tx * 4 + 0], b1 = Kvs[m][tx * 4 + 1];
        float b2 = Kvs[m][tx * 4 + 2], b3 = Kvs[m][tx * 4 + 3];
        acc[0][0] = fmaf(a0, b0, acc[0][0]); acc[0][1] = fmaf(a0, b1, acc[0][1]);
        acc[0][2] = fmaf(a0, b2, acc[0][2]); acc[0][3] = fmaf(a0, b3, acc[0][3]);
        acc[1][0] = fmaf(a1, b0, acc[1][0]); acc[1][1] = fmaf(a1, b1, acc[1][1]);
        acc[1][2] = fmaf(a1, b2, acc[1][2]); acc[1][3] = fmaf(a1, b3, acc[1][3]);
        acc[2][0] = fmaf(a2, b0, acc[2][0]); acc[2][1] = fmaf(a2, b1, acc[2][1]);
        acc[2][2] = fmaf(a2, b2, acc[2][2]); acc[2][3] = fmaf(a2, b3, acc[2][3]);
        acc[3][0] = fmaf(a3, b0, acc[3][0]); acc[3][1] = fmaf(a3, b1, acc[3][1]);
        acc[3][2] = fmaf(a3, b2, acc[3][2]); acc[3][3] = fmaf(a3, b3, acc[3][3]);
        den[0] = fmaf(a0, k1m, den[0]); den[1] = fmaf(a1, k1m, den[1]);
        den[2] = fmaf(a2, k1m, den[2]); den[3] = fmaf(a3, k1m, den[3]);
    }

#pragma unroll
    for (int i = 0; i < 4; ++i) {
        int r = ty * 4 + i;
        float inv = 1.f / (den[i] + EPSV);
        float4 o;
        o.x = acc[i][0] * inv; o.y = acc[i][1] * inv;
        o.z = acc[i][2] * inv; o.w = acc[i][3] * inv;
        uint32_t h0, l0, h1, l1;
        split2h(o.x, o.y, h0, l0);
        split2h(o.z, o.w, h1, l1);
        size_t idx = baseO + (size_t)r * DD + tx * 4;
        *(uint2*)(g_attH + idx) = make_uint2(h0, h1);
        *(uint2*)(g_attL + idx) = make_uint2(l0, l1);
    }
}

// --------------------------- host launch --------------------------------
extern "C" void kernel_launch(void* const* d_in, const int* in_sizes, int n_in,
                              void* d_out, int out_size) {
    const float* x  = (const float*)d_in[0];
    const float* Wq = (const float*)d_in[1];
    const float* Wk = (const float*)d_in[2];
    const float* Wv = (const float*)d_in[3];
    const float* Wo = (const float*)d_in[4];
    float* out = (float*)d_out;

    float* qkv;
    __half *xh, *xl, *ath, *atl, *wt;
    cudaGetSymbolAddress((void**)&qkv, g_QKV);
    cudaGetSymbolAddress((void**)&xh,  g_Xh);
    cudaGetSymbolAddress((void**)&xl,  g_Xl);
    cudaGetSymbolAddress((void**)&ath, g_attH);
    cudaGetSymbolAddress((void**)&atl, g_attL);
    cudaGetSymbolAddress((void**)&wt,  g_Wt);

    cudaFuncSetAttribute(mma_gemm_k,
                         cudaFuncAttributeMaxDynamicSharedMemorySize, GEMM_SMEM);

    // pre-passes
    xsplit_k<<<MLROWS * DD / 1024, 256>>>(x, xh, xl);
    dim3 wg(DD / 32, DD / 32);
    wsplit_k<<<wg, 256>>>(Wq, wt + 0 * (size_t)DD * DD);
    wsplit_k<<<wg, 256>>>(Wk, wt + 1 * (size_t)DD * DD);
    wsplit_k<<<wg, 256>>>(Wv, wt + 2 * (size_t)DD * DD);
    wsplit_k<<<wg, 256>>>(Wo, wt + 3 * (size_t)DD * DD);

    // fused QKV GEMM: N = 3072, phi on cols < 2048 (Q and K blocks)
    dim3 gqkv(NQKV / 256, MLROWS / 128);      // (12, 256)
    mma_gemm_k<<<gqkv, GTHREADS, GEMM_SMEM>>>(xh, xl, wt, qkv, NQKV, 2 * DD);

    kv_part_k<<<dim3(BB * HH, SPLITS), 256>>>();
    kv_reduce_k<<<BB * HH, 256>>>();
    numden_k<<<dim3(BB * HH, LL / 64), 256>>>();

    // output GEMM: N = 1024, no phi
    dim3 gout(DD / 256, MLROWS / 128);        // (4, 256)
    mma_gemm_k<<<gout, GTHREADS, GEMM_SMEM>>>(ath, atl,
                                              wt + 3 * (size_t)DD * DD,
                                              out, DD, 0);
}